// round 1
// baseline (speedup 1.0000x reference)
#include <cuda_runtime.h>
#include <math.h>

// Problem constants
#define B_    256
#define N_    207
#define D_    256      // NU = d
#define DIN_  64
#define CXG_  320      // DIN + NU
#define KC_   1280     // 4 * 320
#define NB_   52992    // B_ * N_
#define QKVLD 768

// ---------------- scratch (device globals; no allocation allowed) ----------------
__device__ float g_s  [(size_t)NB_ * D_];     // transformer input s (b,n,c)
__device__ float g_qkv[(size_t)NB_ * QKVLD];  // qkv
__device__ float g_sc [(size_t)B_ * N_ * N_]; // attention scores
__device__ float g_o  [(size_t)NB_ * D_];     // attn out / ffn hidden (reused)
__device__ float g_s2 [(size_t)NB_ * D_];     // post-LN1
__device__ float g_f1 [(size_t)NB_ * D_];     // proj / ffn2 temp
__device__ float g_s3 [(size_t)NB_ * D_];     // post-LN2
__device__ float g_hn [(size_t)NB_ * D_];     // updated h in (b,n,c)
__device__ float g_z  [(size_t)NB_ * KC_];    // diffusion features (b,n,1280)
__device__ float g_gu [(size_t)NB_ * D_];     // gate u pre-activation (+bias)
__device__ float g_gc [(size_t)NB_ * D_];     // gate c pre-activation (+bias)

// ---------------- kernels ----------------

// s[(b,n),c] = h[b,c,n] + embed[n,c] * mask_last_tp[b,0,n]
__global__ void build_inp(const float* __restrict__ h, const float* __restrict__ embed,
                          const float* __restrict__ mlt) {
    int r = blockIdx.x, c = threadIdx.x;
    int b = r / N_, n = r % N_;
    g_s[(size_t)r * D_ + c] =
        h[((size_t)b * D_ + c) * N_ + n] + embed[(size_t)n * D_ + c] * mlt[(size_t)b * N_ + n];
}

// Big SGEMM: C = A @ B^T + bias, optional relu.
// A: M x K (lda), B: Nc x K (ldb), C: M x Nc (ldc). Requires M%128==0, Nc%128==0, K%16==0.
// grid = (Nc/128, M/128), block = 256 threads, each computes 8x8.
__global__ __launch_bounds__(256) void sgemm_abt(
    const float* __restrict__ A, const float* __restrict__ Bw,
    const float* __restrict__ bias, float* __restrict__ C,
    int K, int lda, int ldb, int ldc, int relu)
{
    __shared__ float As[16][128];
    __shared__ float Bs[16][128];
    int tid = threadIdx.x;
    int tx = tid & 15, ty = tid >> 4;
    int i0 = blockIdx.y * 128, j0 = blockIdx.x * 128;
    float acc[8][8];
#pragma unroll
    for (int i = 0; i < 8; ++i)
#pragma unroll
        for (int j = 0; j < 8; ++j) acc[i][j] = 0.f;

    for (int k0 = 0; k0 < K; k0 += 16) {
#pragma unroll
        for (int l = 0; l < 2; ++l) {
            int f = tid * 2 + l;        // 0..511 float4 index
            int row = f >> 2;
            int kq = (f & 3) * 4;
            float4 va = *(const float4*)&A[(size_t)(i0 + row) * lda + k0 + kq];
            As[kq + 0][row] = va.x; As[kq + 1][row] = va.y;
            As[kq + 2][row] = va.z; As[kq + 3][row] = va.w;
            float4 vb = *(const float4*)&Bw[(size_t)(j0 + row) * ldb + k0 + kq];
            Bs[kq + 0][row] = vb.x; Bs[kq + 1][row] = vb.y;
            Bs[kq + 2][row] = vb.z; Bs[kq + 3][row] = vb.w;
        }
        __syncthreads();
#pragma unroll
        for (int k = 0; k < 16; ++k) {
            float a[8], b[8];
            *(float4*)&a[0] = *(const float4*)&As[k][ty * 8];
            *(float4*)&a[4] = *(const float4*)&As[k][ty * 8 + 4];
            *(float4*)&b[0] = *(const float4*)&Bs[k][tx * 8];
            *(float4*)&b[4] = *(const float4*)&Bs[k][tx * 8 + 4];
#pragma unroll
            for (int ii = 0; ii < 8; ++ii)
#pragma unroll
                for (int jj = 0; jj < 8; ++jj) acc[ii][jj] += a[ii] * b[jj];
        }
        __syncthreads();
    }
#pragma unroll
    for (int ii = 0; ii < 8; ++ii) {
        int i = i0 + ty * 8 + ii;
#pragma unroll
        for (int jj = 0; jj < 8; ++jj) {
            int j = j0 + tx * 8 + jj;
            float v = acc[ii][jj] + (bias ? bias[j] : 0.f);
            if (relu) v = fmaxf(v, 0.f);
            C[(size_t)i * ldc + j] = v;
        }
    }
}

// Batched small GEMM: C[b] = alpha * A[b] @ op(B[b]); op = B (NN) or B^T (transB).
// 32x32 tile, block (16,16), 2x2 per thread, bounds-checked.
__global__ void bgemm(const float* __restrict__ A, const float* __restrict__ Bm,
                      float* __restrict__ C,
                      int M, int Nc, int K, int lda, int ldb, int ldc,
                      long long sA, long long sB, long long sC,
                      float alpha, int transB)
{
    int bz = blockIdx.z;
    const float* Ab = A + (size_t)bz * sA;
    const float* Bb = Bm + (size_t)bz * sB;
    float* Cb = C + (size_t)bz * sC;
    __shared__ float As[32][17];
    __shared__ float Bs[16][33];
    int tx = threadIdx.x, ty = threadIdx.y;
    int tid = ty * 16 + tx;
    int i0 = blockIdx.y * 32, j0 = blockIdx.x * 32;
    float acc00 = 0.f, acc01 = 0.f, acc10 = 0.f, acc11 = 0.f;

    for (int k0 = 0; k0 < K; k0 += 16) {
#pragma unroll
        for (int l = 0; l < 2; ++l) {
            int e = tid + l * 256;
            {   // A tile: 32 rows x 16 k
                int r = e >> 4, kk = e & 15;
                As[r][kk] = (i0 + r < M && k0 + kk < K)
                            ? Ab[(size_t)(i0 + r) * lda + k0 + kk] : 0.f;
            }
            if (transB) {
                int jj = e >> 4, kk = e & 15;
                Bs[kk][jj] = (j0 + jj < Nc && k0 + kk < K)
                             ? Bb[(size_t)(j0 + jj) * ldb + k0 + kk] : 0.f;
            } else {
                int kk = e >> 5, jj = e & 31;
                Bs[kk][jj] = (j0 + jj < Nc && k0 + kk < K)
                             ? Bb[(size_t)(k0 + kk) * ldb + j0 + jj] : 0.f;
            }
        }
        __syncthreads();
#pragma unroll
        for (int kk = 0; kk < 16; ++kk) {
            float a0 = As[ty * 2][kk], a1 = As[ty * 2 + 1][kk];
            float b0 = Bs[kk][tx * 2], b1 = Bs[kk][tx * 2 + 1];
            acc00 += a0 * b0; acc01 += a0 * b1;
            acc10 += a1 * b0; acc11 += a1 * b1;
        }
        __syncthreads();
    }
    int i = i0 + ty * 2, j = j0 + tx * 2;
    if (i < M) {
        if (j     < Nc) Cb[(size_t)i * ldc + j]     = alpha * acc00;
        if (j + 1 < Nc) Cb[(size_t)i * ldc + j + 1] = alpha * acc01;
    }
    if (i + 1 < M) {
        if (j     < Nc) Cb[(size_t)(i + 1) * ldc + j]     = alpha * acc10;
        if (j + 1 < Nc) Cb[(size_t)(i + 1) * ldc + j + 1] = alpha * acc11;
    }
}

// Row softmax over 207 entries; one warp per row, 8 warps per block.
__global__ void softmax_rows(float* __restrict__ sc) {
    int row = blockIdx.x * 8 + threadIdx.y;
    float* p = sc + (size_t)row * N_;
    int lane = threadIdx.x;
    float mx = -1e30f;
    for (int j = lane; j < N_; j += 32) mx = fmaxf(mx, p[j]);
#pragma unroll
    for (int o = 16; o > 0; o >>= 1) mx = fmaxf(mx, __shfl_xor_sync(0xffffffffu, mx, o));
    float sum = 0.f;
    for (int j = lane; j < N_; j += 32) { float e = expf(p[j] - mx); p[j] = e; sum += e; }
#pragma unroll
    for (int o = 16; o > 0; o >>= 1) sum += __shfl_xor_sync(0xffffffffu, sum, o);
    float inv = 1.f / sum;
    for (int j = lane; j < N_; j += 32) p[j] *= inv;
}

// out[r,c] = LayerNorm_c(a[r,c] + bsrc[r,c]) * w[c] + bb[c]
__global__ void add_ln(const float* __restrict__ a, const float* __restrict__ bsrc,
                       const float* __restrict__ w, const float* __restrict__ bb,
                       float* __restrict__ outp) {
    int r = blockIdx.x, c = threadIdx.x;
    size_t idx = (size_t)r * D_ + c;
    float v = a[idx] + bsrc[idx];
    __shared__ float red[256];
    red[c] = v; __syncthreads();
#pragma unroll
    for (int s = 128; s > 0; s >>= 1) { if (c < s) red[c] += red[c + s]; __syncthreads(); }
    float mu = red[0] * (1.f / 256.f);
    __syncthreads();
    float dv = v - mu;
    red[c] = dv * dv; __syncthreads();
#pragma unroll
    for (int s = 128; s > 0; s >>= 1) { if (c < s) red[c] += red[c + s]; __syncthreads(); }
    float var = red[0] * (1.f / 256.f);
    outp[idx] = dv * rsqrtf(var + 1e-5f) * w[c] + bb[c];
}

// h update + assemble first diffusion block z[:, :320]
__global__ void make_h_xg(const float* __restrict__ h, const float* __restrict__ x,
                          const float* __restrict__ dt, const int* __restrict__ step) {
    int r = blockIdx.x, c = threadIdx.x;
    int b = r / N_, n = r % N_;
    float hv = h[((size_t)b * D_ + c) * N_ + n];
    float hn;
    if (*step != 0) {
        float d = dt[b];
        hn = sqrtf(1.f - d) * hv - sqrtf(d) * tanhf(g_s3[(size_t)r * D_ + c]);
    } else {
        hn = hv;
    }
    g_hn[(size_t)r * D_ + c] = hn;
    g_z[(size_t)r * KC_ + DIN_ + c] = hn;
    if (c < DIN_)
        g_z[(size_t)r * KC_ + c] = x[((size_t)b * DIN_ + c) * N_ + n];
}

// out[b,o,n] = u*hn + (1-u)*c ; u=sigmoid(gu), c=tanh(gc); transpose (b,n,o)->(b,o,n)
__global__ void final_combine(float* __restrict__ outp) {
    int b = blockIdx.z;
    int o0 = blockIdx.y * 32, n0 = blockIdx.x * 32;
    __shared__ float t[32][33];
    int tx = threadIdx.x, ty = threadIdx.y; // (32,8)
#pragma unroll
    for (int s4 = 0; s4 < 4; ++s4) {
        int nl = ty + s4 * 8;
        int n = n0 + nl;
        float val = 0.f;
        if (n < N_) {
            size_t idx = ((size_t)(b * N_ + n)) * D_ + o0 + tx;
            float uu = 1.f / (1.f + expf(-g_gu[idx]));
            float cc = tanhf(g_gc[idx]);
            val = uu * g_hn[idx] + (1.f - uu) * cc;
        }
        t[nl][tx] = val;
    }
    __syncthreads();
#pragma unroll
    for (int s4 = 0; s4 < 4; ++s4) {
        int ol = ty + s4 * 8;
        int n = n0 + tx;
        if (n < N_)
            outp[((size_t)(b * D_ + o0 + ol)) * N_ + n] = t[tx][ol];
    }
}

// ---------------- launcher ----------------
extern "C" void kernel_launch(void* const* d_in, const int* in_sizes, int n_in,
                              void* d_out, int out_size) {
    const float* x          = (const float*)d_in[0];
    const float* delta_t    = (const float*)d_in[1];
    const float* h          = (const float*)d_in[2];
    const float* adj        = (const float*)d_in[3];
    // d_in[4] mask: unused
    const float* mlt        = (const float*)d_in[5];
    // d_in[6] time_encoding: unused
    const int*   step       = (const int*)d_in[7];
    const float* embed      = (const float*)d_in[8];
    const float* in_proj_w  = (const float*)d_in[9];
    const float* in_proj_b  = (const float*)d_in[10];
    const float* out_proj_w = (const float*)d_in[11];
    const float* out_proj_b = (const float*)d_in[12];
    const float* ln1_w      = (const float*)d_in[13];
    const float* ln1_b      = (const float*)d_in[14];
    const float* ln2_w      = (const float*)d_in[15];
    const float* ln2_b      = (const float*)d_in[16];
    const float* ffn_w1     = (const float*)d_in[17];
    const float* ffn_b1     = (const float*)d_in[18];
    const float* ffn_w2     = (const float*)d_in[19];
    const float* ffn_b2     = (const float*)d_in[20];
    const float* W_u        = (const float*)d_in[21];
    const float* b_u        = (const float*)d_in[22];
    const float* W_c        = (const float*)d_in[23];
    const float* b_c        = (const float*)d_in[24];
    float* outp = (float*)d_out;

    void *vp;
    cudaGetSymbolAddress(&vp, g_s);   float* ps  = (float*)vp;
    cudaGetSymbolAddress(&vp, g_qkv); float* pq  = (float*)vp;
    cudaGetSymbolAddress(&vp, g_sc);  float* psc = (float*)vp;
    cudaGetSymbolAddress(&vp, g_o);   float* po  = (float*)vp;
    cudaGetSymbolAddress(&vp, g_s2);  float* ps2 = (float*)vp;
    cudaGetSymbolAddress(&vp, g_f1);  float* pf1 = (float*)vp;
    cudaGetSymbolAddress(&vp, g_s3);  float* ps3 = (float*)vp;
    cudaGetSymbolAddress(&vp, g_z);   float* pz  = (float*)vp;
    cudaGetSymbolAddress(&vp, g_gu);  float* pgu = (float*)vp;
    cudaGetSymbolAddress(&vp, g_gc);  float* pgc = (float*)vp;

    // 1. transformer input
    build_inp<<<NB_, 256>>>(h, embed, mlt);

    // 2. QKV projection: (52992 x 256) @ (768 x 256)^T
    sgemm_abt<<<dim3(768 / 128, NB_ / 128), 256>>>(ps, in_proj_w, in_proj_b, pq,
                                                   256, 256, 256, QKVLD, 0);

    // 3. attention scores: per-batch Q @ K^T / 16
    bgemm<<<dim3(7, 7, B_), dim3(16, 16)>>>(pq, pq + 256, psc,
        N_, N_, 256, QKVLD, QKVLD, N_,
        (long long)N_ * QKVLD, (long long)N_ * QKVLD, (long long)N_ * N_,
        1.f / 16.f, 1);

    // 4. softmax over keys
    softmax_rows<<<NB_ / 8, dim3(32, 8)>>>(psc);

    // 5. attn @ V
    bgemm<<<dim3(8, 7, B_), dim3(16, 16)>>>(psc, pq + 512, po,
        N_, 256, N_, N_, QKVLD, 256,
        (long long)N_ * N_, (long long)N_ * QKVLD, (long long)N_ * 256,
        1.f, 0);

    // 6. out projection
    sgemm_abt<<<dim3(2, NB_ / 128), 256>>>(po, out_proj_w, out_proj_b, pf1,
                                           256, 256, 256, 256, 0);

    // 7. LN1(s + o)
    add_ln<<<NB_, 256>>>(ps, pf1, ln1_w, ln1_b, ps2);

    // 8. FFN
    sgemm_abt<<<dim3(2, NB_ / 128), 256>>>(ps2, ffn_w1, ffn_b1, po,
                                           256, 256, 256, 256, 1);
    sgemm_abt<<<dim3(2, NB_ / 128), 256>>>(po, ffn_w2, ffn_b2, pf1,
                                           256, 256, 256, 256, 0);

    // 9. LN2(s2 + f)
    add_ln<<<NB_, 256>>>(ps2, pf1, ln2_w, ln2_b, ps3);

    // 10. h update + z block 0
    make_h_xg<<<NB_, 256>>>(h, x, delta_t, step);

    // 11. spatial diffusion: z_k = adj @ z_{k-1} per batch, k = 1..3
    for (int k = 1; k <= 3; ++k) {
        bgemm<<<dim3(10, 7, B_), dim3(16, 16)>>>(adj, pz + (size_t)(k - 1) * CXG_,
            pz + (size_t)k * CXG_,
            N_, CXG_, N_, N_, KC_, KC_,
            0LL, (long long)N_ * KC_, (long long)N_ * KC_,
            1.f, 0);
    }

    // 12. gate GEMMs: (52992 x 1280) @ (256 x 1280)^T + bias
    sgemm_abt<<<dim3(2, NB_ / 128), 256>>>(pz, W_u, b_u, pgu, KC_, KC_, KC_, 256, 0);
    sgemm_abt<<<dim3(2, NB_ / 128), 256>>>(pz, W_c, b_c, pgc, KC_, KC_, KC_, 256, 0);

    // 13. gated combine + transpose to (B, NU, N)
    final_combine<<<dim3(7, 8, B_), dim3(32, 8)>>>(outp);
}

// round 2
// speedup vs baseline: 1.5077x; 1.5077x over previous
#include <cuda_runtime.h>
#include <math.h>

// Problem constants
#define B_    256
#define N_    207
#define D_    256
#define DIN_  64
#define CXG_  320
#define KC_   1280
#define NB_   52992
#define QKVLD 768

// ---------------- scratch ----------------
__device__ float g_s  [(size_t)NB_ * D_];
__device__ float g_qkv[(size_t)NB_ * QKVLD];
__device__ float g_sc [(size_t)B_ * N_ * N_];
__device__ float g_o  [(size_t)NB_ * D_];
__device__ float g_s2 [(size_t)NB_ * D_];
__device__ float g_f1 [(size_t)NB_ * D_];
__device__ float g_s3 [(size_t)NB_ * D_];
__device__ float g_hn [(size_t)NB_ * D_];
__device__ float g_z  [(size_t)NB_ * KC_];
__device__ float g_gu [(size_t)NB_ * D_];
__device__ float g_gc [(size_t)NB_ * D_];

// ---------------- helpers ----------------
__device__ __forceinline__ unsigned f2tf(float f) {
    unsigned r;
    asm("cvt.rna.tf32.f32 %0, %1;" : "=r"(r) : "f"(f));
    return r;
}

__device__ __forceinline__ void mma_tf32(float* c, const unsigned* a, const unsigned* b) {
    asm volatile(
        "mma.sync.aligned.m16n8k8.row.col.f32.tf32.tf32.f32 "
        "{%0,%1,%2,%3}, {%4,%5,%6,%7}, {%8,%9}, {%0,%1,%2,%3};\n"
        : "+f"(c[0]), "+f"(c[1]), "+f"(c[2]), "+f"(c[3])
        : "r"(a[0]), "r"(a[1]), "r"(a[2]), "r"(a[3]), "r"(b[0]), "r"(b[1]));
}

// ---------------- TF32 tensor-core GEMM ----------------
// C = alpha * A @ op(B) + bias, optional relu. op(B)=B^T if transB (B is Nc x K
// row-major), else B (K x Nc row-major). Batched via blockIdx.z with strides.
// Tile 128x128, k-chunk 32, 8 warps (2 x 4), warp tile 64x32, mma m16n8k8.
// Smem k-major, stride 136 (conflict-free fragment reads, 16B-aligned rows).
__global__ __launch_bounds__(256) void mma_gemm(
    const float* __restrict__ A, const float* __restrict__ Bm,
    const float* __restrict__ bias, float* __restrict__ C,
    int M, int Nc, int K, int lda, int ldb, int ldc,
    long long sA, long long sB, long long sC,
    float alpha, int transB, int relu)
{
    __shared__ unsigned As[32 * 136];
    __shared__ unsigned Bs[32 * 136];

    const float* Ab = A  + (size_t)blockIdx.z * sA;
    const float* Bb = Bm + (size_t)blockIdx.z * sB;
    float*       Cb = C  + (size_t)blockIdx.z * sC;

    const int tid  = threadIdx.x;
    const int lane = tid & 31;
    const int wid  = tid >> 5;
    const int wr   = (wid & 1) * 64;   // warp row offset in tile
    const int wc   = (wid >> 1) * 32;  // warp col offset in tile
    const int g    = lane >> 2;
    const int t    = lane & 3;

    const int i0 = blockIdx.y * 128;
    const int j0 = blockIdx.x * 128;

    const bool vecA = ((lda & 3) == 0);
    const bool vecB = ((ldb & 3) == 0);

    float acc[4][4][4];
#pragma unroll
    for (int mi = 0; mi < 4; ++mi)
#pragma unroll
        for (int ni = 0; ni < 4; ++ni)
#pragma unroll
            for (int q = 0; q < 4; ++q) acc[mi][ni][q] = 0.f;

    for (int k0 = 0; k0 < K; k0 += 32) {
        const bool kfull = (k0 + 32 <= K);

        // ---- load A tile: 128 rows x 32 k, store As[k][row] ----
        if (vecA && kfull) {
#pragma unroll
            for (int l = 0; l < 4; ++l) {
                int e = tid + l * 256;        // 0..1023 float4 units
                int row = e >> 3;
                int kq = (e & 7) * 4;
                int gr = i0 + row; if (gr > M - 1) gr = M - 1;
                float4 v = *(const float4*)&Ab[(size_t)gr * lda + k0 + kq];
                As[(kq + 0) * 136 + row] = f2tf(v.x);
                As[(kq + 1) * 136 + row] = f2tf(v.y);
                As[(kq + 2) * 136 + row] = f2tf(v.z);
                As[(kq + 3) * 136 + row] = f2tf(v.w);
            }
        } else {
#pragma unroll
            for (int l = 0; l < 16; ++l) {
                int e = tid + l * 256;        // 0..4095
                int row = e >> 5;
                int kk = e & 31;
                int gr = i0 + row; if (gr > M - 1) gr = M - 1;
                int gk = k0 + kk;
                float v = (gk < K) ? Ab[(size_t)gr * lda + gk] : 0.f;
                As[kk * 136 + row] = f2tf(v);
            }
        }

        // ---- load B tile -> Bs[k][n] ----
        if (transB) {
            if (vecB && kfull) {
#pragma unroll
                for (int l = 0; l < 4; ++l) {
                    int e = tid + l * 256;
                    int row = e >> 3;          // n index
                    int kq = (e & 7) * 4;
                    int gr = j0 + row; if (gr > Nc - 1) gr = Nc - 1;
                    float4 v = *(const float4*)&Bb[(size_t)gr * ldb + k0 + kq];
                    Bs[(kq + 0) * 136 + row] = f2tf(v.x);
                    Bs[(kq + 1) * 136 + row] = f2tf(v.y);
                    Bs[(kq + 2) * 136 + row] = f2tf(v.z);
                    Bs[(kq + 3) * 136 + row] = f2tf(v.w);
                }
            } else {
#pragma unroll
                for (int l = 0; l < 16; ++l) {
                    int e = tid + l * 256;
                    int row = e >> 5;
                    int kk = e & 31;
                    int gr = j0 + row; if (gr > Nc - 1) gr = Nc - 1;
                    int gk = k0 + kk;
                    float v = (gk < K) ? Bb[(size_t)gr * ldb + gk] : 0.f;
                    Bs[kk * 136 + row] = f2tf(v);
                }
            }
        } else {  // NN: B is K x Nc row-major
            if (vecB && kfull) {
#pragma unroll
                for (int l = 0; l < 4; ++l) {
                    int e = tid + l * 256;
                    int kk = e >> 5;
                    int nq = (e & 31) * 4;
                    float4 v = *(const float4*)&Bb[(size_t)(k0 + kk) * ldb + j0 + nq];
                    unsigned* dst = &Bs[kk * 136 + nq];
                    dst[0] = f2tf(v.x); dst[1] = f2tf(v.y);
                    dst[2] = f2tf(v.z); dst[3] = f2tf(v.w);
                }
            } else {
#pragma unroll
                for (int l = 0; l < 16; ++l) {
                    int e = tid + l * 256;
                    int kk = e >> 7;
                    int n = e & 127;
                    int gk = k0 + kk;
                    int gn = j0 + n; if (gn > Nc - 1) gn = Nc - 1;
                    float v = (gk < K) ? Bb[(size_t)gk * ldb + gn] : 0.f;
                    Bs[kk * 136 + n] = f2tf(v);
                }
            }
        }
        __syncthreads();

        // ---- compute ----
#pragma unroll
        for (int k8 = 0; k8 < 4; ++k8) {
            int kb = k8 * 8;
            unsigned af[4][4];
#pragma unroll
            for (int mi = 0; mi < 4; ++mi) {
                int r = wr + mi * 16 + g;
                af[mi][0] = As[(kb + t) * 136 + r];
                af[mi][1] = As[(kb + t) * 136 + r + 8];
                af[mi][2] = As[(kb + t + 4) * 136 + r];
                af[mi][3] = As[(kb + t + 4) * 136 + r + 8];
            }
            unsigned bf[4][2];
#pragma unroll
            for (int ni = 0; ni < 4; ++ni) {
                int cc = wc + ni * 8 + g;
                bf[ni][0] = Bs[(kb + t) * 136 + cc];
                bf[ni][1] = Bs[(kb + t + 4) * 136 + cc];
            }
#pragma unroll
            for (int mi = 0; mi < 4; ++mi)
#pragma unroll
                for (int ni = 0; ni < 4; ++ni)
                    mma_tf32(acc[mi][ni], af[mi], bf[ni]);
        }
        __syncthreads();
    }

    // ---- epilogue ----
#pragma unroll
    for (int mi = 0; mi < 4; ++mi) {
        int r0 = i0 + wr + mi * 16 + g;
#pragma unroll
        for (int ni = 0; ni < 4; ++ni) {
            int c0 = j0 + wc + ni * 8 + 2 * t;
            float b0v = 0.f, b1v = 0.f;
            if (bias) {
                if (c0 < Nc)     b0v = bias[c0];
                if (c0 + 1 < Nc) b1v = bias[c0 + 1];
            }
            float v00 = alpha * acc[mi][ni][0] + b0v;
            float v01 = alpha * acc[mi][ni][1] + b1v;
            float v10 = alpha * acc[mi][ni][2] + b0v;
            float v11 = alpha * acc[mi][ni][3] + b1v;
            if (relu) {
                v00 = fmaxf(v00, 0.f); v01 = fmaxf(v01, 0.f);
                v10 = fmaxf(v10, 0.f); v11 = fmaxf(v11, 0.f);
            }
            if (r0 < M) {
                if (c0 < Nc)     Cb[(size_t)r0 * ldc + c0]     = v00;
                if (c0 + 1 < Nc) Cb[(size_t)r0 * ldc + c0 + 1] = v01;
            }
            if (r0 + 8 < M) {
                if (c0 < Nc)     Cb[(size_t)(r0 + 8) * ldc + c0]     = v10;
                if (c0 + 1 < Nc) Cb[(size_t)(r0 + 8) * ldc + c0 + 1] = v11;
            }
        }
    }
}

// ---------------- elementwise kernels ----------------

__global__ void build_inp(const float* __restrict__ h, const float* __restrict__ embed,
                          const float* __restrict__ mlt) {
    int r = blockIdx.x, c = threadIdx.x;
    int b = r / N_, n = r % N_;
    g_s[(size_t)r * D_ + c] =
        h[((size_t)b * D_ + c) * N_ + n] + embed[(size_t)n * D_ + c] * mlt[(size_t)b * N_ + n];
}

__global__ void softmax_rows(float* __restrict__ sc) {
    int row = blockIdx.x * 8 + threadIdx.y;
    float* p = sc + (size_t)row * N_;
    int lane = threadIdx.x;
    float mx = -1e30f;
    for (int j = lane; j < N_; j += 32) mx = fmaxf(mx, p[j]);
#pragma unroll
    for (int o = 16; o > 0; o >>= 1) mx = fmaxf(mx, __shfl_xor_sync(0xffffffffu, mx, o));
    float sum = 0.f;
    for (int j = lane; j < N_; j += 32) { float e = expf(p[j] - mx); p[j] = e; sum += e; }
#pragma unroll
    for (int o = 16; o > 0; o >>= 1) sum += __shfl_xor_sync(0xffffffffu, sum, o);
    float inv = 1.f / sum;
    for (int j = lane; j < N_; j += 32) p[j] *= inv;
}

__global__ void add_ln(const float* __restrict__ a, const float* __restrict__ bsrc,
                       const float* __restrict__ w, const float* __restrict__ bb,
                       float* __restrict__ outp) {
    int r = blockIdx.x, c = threadIdx.x;
    size_t idx = (size_t)r * D_ + c;
    float v = a[idx] + bsrc[idx];
    __shared__ float red[256];
    red[c] = v; __syncthreads();
#pragma unroll
    for (int s = 128; s > 0; s >>= 1) { if (c < s) red[c] += red[c + s]; __syncthreads(); }
    float mu = red[0] * (1.f / 256.f);
    __syncthreads();
    float dv = v - mu;
    red[c] = dv * dv; __syncthreads();
#pragma unroll
    for (int s = 128; s > 0; s >>= 1) { if (c < s) red[c] += red[c + s]; __syncthreads(); }
    float var = red[0] * (1.f / 256.f);
    outp[idx] = dv * rsqrtf(var + 1e-5f) * w[c] + bb[c];
}

__global__ void make_h_xg(const float* __restrict__ h, const float* __restrict__ x,
                          const float* __restrict__ dt, const int* __restrict__ step) {
    int r = blockIdx.x, c = threadIdx.x;
    int b = r / N_, n = r % N_;
    float hv = h[((size_t)b * D_ + c) * N_ + n];
    float hn;
    if (*step != 0) {
        float d = dt[b];
        hn = sqrtf(1.f - d) * hv - sqrtf(d) * tanhf(g_s3[(size_t)r * D_ + c]);
    } else {
        hn = hv;
    }
    g_hn[(size_t)r * D_ + c] = hn;
    g_z[(size_t)r * KC_ + DIN_ + c] = hn;
    if (c < DIN_)
        g_z[(size_t)r * KC_ + c] = x[((size_t)b * DIN_ + c) * N_ + n];
}

__global__ void final_combine(float* __restrict__ outp) {
    int b = blockIdx.z;
    int o0 = blockIdx.y * 32, n0 = blockIdx.x * 32;
    __shared__ float tbuf[32][33];
    int tx = threadIdx.x, ty = threadIdx.y;
#pragma unroll
    for (int s4 = 0; s4 < 4; ++s4) {
        int nl = ty + s4 * 8;
        int n = n0 + nl;
        float val = 0.f;
        if (n < N_) {
            size_t idx = ((size_t)(b * N_ + n)) * D_ + o0 + tx;
            float uu = 1.f / (1.f + expf(-g_gu[idx]));
            float cc = tanhf(g_gc[idx]);
            val = uu * g_hn[idx] + (1.f - uu) * cc;
        }
        tbuf[nl][tx] = val;
    }
    __syncthreads();
#pragma unroll
    for (int s4 = 0; s4 < 4; ++s4) {
        int ol = ty + s4 * 8;
        int n = n0 + tx;
        if (n < N_)
            outp[((size_t)(b * D_ + o0 + ol)) * N_ + n] = tbuf[tx][ol];
    }
}

// ---------------- launcher ----------------
extern "C" void kernel_launch(void* const* d_in, const int* in_sizes, int n_in,
                              void* d_out, int out_size) {
    const float* x          = (const float*)d_in[0];
    const float* delta_t    = (const float*)d_in[1];
    const float* h          = (const float*)d_in[2];
    const float* adj        = (const float*)d_in[3];
    const float* mlt        = (const float*)d_in[5];
    const int*   step       = (const int*)d_in[7];
    const float* embed      = (const float*)d_in[8];
    const float* in_proj_w  = (const float*)d_in[9];
    const float* in_proj_b  = (const float*)d_in[10];
    const float* out_proj_w = (const float*)d_in[11];
    const float* out_proj_b = (const float*)d_in[12];
    const float* ln1_w      = (const float*)d_in[13];
    const float* ln1_b      = (const float*)d_in[14];
    const float* ln2_w      = (const float*)d_in[15];
    const float* ln2_b      = (const float*)d_in[16];
    const float* ffn_w1     = (const float*)d_in[17];
    const float* ffn_b1     = (const float*)d_in[18];
    const float* ffn_w2     = (const float*)d_in[19];
    const float* ffn_b2     = (const float*)d_in[20];
    const float* W_u        = (const float*)d_in[21];
    const float* b_u        = (const float*)d_in[22];
    const float* W_c        = (const float*)d_in[23];
    const float* b_c        = (const float*)d_in[24];
    float* outp = (float*)d_out;

    void *vp;
    cudaGetSymbolAddress(&vp, g_s);   float* ps  = (float*)vp;
    cudaGetSymbolAddress(&vp, g_qkv); float* pq  = (float*)vp;
    cudaGetSymbolAddress(&vp, g_sc);  float* psc = (float*)vp;
    cudaGetSymbolAddress(&vp, g_o);   float* po  = (float*)vp;
    cudaGetSymbolAddress(&vp, g_s2);  float* ps2 = (float*)vp;
    cudaGetSymbolAddress(&vp, g_f1);  float* pf1 = (float*)vp;
    cudaGetSymbolAddress(&vp, g_s3);  float* ps3 = (float*)vp;
    cudaGetSymbolAddress(&vp, g_z);   float* pz  = (float*)vp;
    cudaGetSymbolAddress(&vp, g_gu);  float* pgu = (float*)vp;
    cudaGetSymbolAddress(&vp, g_gc);  float* pgc = (float*)vp;

    // 1. transformer input
    build_inp<<<NB_, 256>>>(h, embed, mlt);

    // 2. QKV: (52992 x 256) @ (768 x 256)^T + bias
    mma_gemm<<<dim3(6, 414, 1), 256>>>(ps, in_proj_w, in_proj_b, pq,
        NB_, QKVLD, 256, 256, 256, QKVLD, 0, 0, 0, 1.f, 1, 0);

    // 3. scores: per-batch Q @ K^T / 16
    mma_gemm<<<dim3(2, 2, B_), 256>>>(pq, pq + 256, nullptr, psc,
        N_, N_, 256, QKVLD, QKVLD, N_,
        (long long)N_ * QKVLD, (long long)N_ * QKVLD, (long long)N_ * N_,
        1.f / 16.f, 1, 0);

    // 4. softmax
    softmax_rows<<<NB_ / 8, dim3(32, 8)>>>(psc);

    // 5. attn @ V (NN)
    mma_gemm<<<dim3(2, 2, B_), 256>>>(psc, pq + 512, nullptr, po,
        N_, 256, N_, N_, QKVLD, 256,
        (long long)N_ * N_, (long long)N_ * QKVLD, (long long)N_ * 256,
        1.f, 0, 0);

    // 6. out projection
    mma_gemm<<<dim3(2, 414, 1), 256>>>(po, out_proj_w, out_proj_b, pf1,
        NB_, 256, 256, 256, 256, 256, 0, 0, 0, 1.f, 1, 0);

    // 7. LN1(s + o)
    add_ln<<<NB_, 256>>>(ps, pf1, ln1_w, ln1_b, ps2);

    // 8. FFN
    mma_gemm<<<dim3(2, 414, 1), 256>>>(ps2, ffn_w1, ffn_b1, po,
        NB_, 256, 256, 256, 256, 256, 0, 0, 0, 1.f, 1, 1);
    mma_gemm<<<dim3(2, 414, 1), 256>>>(po, ffn_w2, ffn_b2, pf1,
        NB_, 256, 256, 256, 256, 256, 0, 0, 0, 1.f, 1, 0);

    // 9. LN2(s2 + f)
    add_ln<<<NB_, 256>>>(ps2, pf1, ln2_w, ln2_b, ps3);

    // 10. h update + z block 0
    make_h_xg<<<NB_, 256>>>(h, x, delta_t, step);

    // 11. diffusion: z_k = adj @ z_{k-1} per batch (NN)
    for (int k = 1; k <= 3; ++k) {
        mma_gemm<<<dim3(3, 2, B_), 256>>>(adj, pz + (size_t)(k - 1) * CXG_,
            nullptr, pz + (size_t)k * CXG_,
            N_, CXG_, N_, N_, KC_, KC_,
            0LL, (long long)N_ * KC_, (long long)N_ * KC_,
            1.f, 0, 0);
    }

    // 12. gates: (52992 x 1280) @ (256 x 1280)^T + bias
    mma_gemm<<<dim3(2, 414, 1), 256>>>(pz, W_u, b_u, pgu,
        NB_, 256, KC_, KC_, KC_, 256, 0, 0, 0, 1.f, 1, 0);
    mma_gemm<<<dim3(2, 414, 1), 256>>>(pz, W_c, b_c, pgc,
        NB_, 256, KC_, KC_, KC_, 256, 0, 0, 0, 1.f, 1, 0);

    // 13. gated combine + transpose
    final_combine<<<dim3(7, 8, B_), dim3(32, 8)>>>(outp);
}

// round 3
// speedup vs baseline: 2.6260x; 1.7417x over previous
#include <cuda_runtime.h>
#include <math.h>

// Problem constants
#define B_    256
#define N_    207
#define D_    256
#define DIN_  64
#define CXG_  320
#define KC_   1280
#define NB_   52992
#define QKVLD 768
#define SCLD  208   // padded ld for scores / adj

// ---------------- scratch ----------------
__device__ float g_s   [(size_t)NB_ * D_];
__device__ float g_qkv [(size_t)NB_ * QKVLD];
__device__ float g_sc  [(size_t)B_ * N_ * SCLD + 256];
__device__ float g_adjp[(size_t)N_ * SCLD];
__device__ float g_o   [(size_t)NB_ * D_];
__device__ float g_s2  [(size_t)NB_ * D_];
__device__ float g_f1  [(size_t)NB_ * D_];
__device__ float g_s3  [(size_t)NB_ * D_];
__device__ float g_hn  [(size_t)NB_ * D_];
__device__ float g_z   [(size_t)NB_ * KC_];
__device__ float g_gu  [(size_t)NB_ * D_];
__device__ float g_gc  [(size_t)NB_ * D_];

// ---------------- helpers ----------------
__device__ __forceinline__ unsigned f2tf(float f) {
    unsigned r;
    asm("cvt.rna.tf32.f32 %0, %1;" : "=r"(r) : "f"(f));
    return r;
}

__device__ __forceinline__ void mma_tf32(float* c, const unsigned* a, const unsigned* b) {
    asm volatile(
        "mma.sync.aligned.m16n8k8.row.col.f32.tf32.tf32.f32 "
        "{%0,%1,%2,%3}, {%4,%5,%6,%7}, {%8,%9}, {%0,%1,%2,%3};\n"
        : "+f"(c[0]), "+f"(c[1]), "+f"(c[2]), "+f"(c[3])
        : "r"(a[0]), "r"(a[1]), "r"(a[2]), "r"(a[3]), "r"(b[0]), "r"(b[1]));
}

__device__ __forceinline__ void cpa16(float* dst, const float* src, int srcbytes) {
    unsigned d = (unsigned)__cvta_generic_to_shared(dst);
    asm volatile("cp.async.cg.shared.global [%0], [%1], 16, %2;\n"
                 :: "r"(d), "l"(src), "r"(srcbytes));
}
__device__ __forceinline__ void cp_commit() {
    asm volatile("cp.async.commit_group;\n" ::: "memory");
}
template <int NGRP>
__device__ __forceinline__ void cp_wait() {
    asm volatile("cp.async.wait_group %0;\n" :: "n"(NGRP) : "memory");
}

// ---------------- TF32 tensor-core GEMM ----------------
// C = alpha * A @ op(B) + bias, optional relu. transB: B is Nc x K row-major;
// else B is K x Nc row-major. Batched via blockIdx.z with strides.
// BM=128, BN template (256: 8 warps / 128: 4 warps), BK=32, warp tile 64x64,
// 3-stage cp.async pipeline. All global loads must be 16B-aligned rows (lda/ldb %4==0).
template<int BN>
__device__ __forceinline__ void load_chunk(
    float* As, float* Bs, const float* Ab, const float* Bb,
    int i0, int j0, int M, int Nc, int K, int lda, int ldb,
    int k0, int tid, int transB)
{
    constexpr int NT = (BN == 256) ? 256 : 128;
    // A tile 128 x 32 -> As[m][k], stride 36
#pragma unroll
    for (int l = 0; l < 1024 / NT; ++l) {
        int e = tid + l * NT;
        int row = e >> 3, kq = (e & 7) * 4;
        int gr = i0 + row; if (gr > M - 1) gr = M - 1;
        int gk = k0 + kq;
        int rem = K - gk;
        int bytes = rem >= 4 ? 16 : (rem > 0 ? rem * 4 : 0);
        const float* src = Ab + (size_t)gr * lda + (bytes ? gk : 0);
        cpa16(As + row * 36 + kq, src, bytes);
    }
    if (transB) {
        // B tile BN x 32 -> Bs[n][k], stride 36
#pragma unroll
        for (int l = 0; l < BN * 8 / NT; ++l) {
            int e = tid + l * NT;
            int row = e >> 3, kq = (e & 7) * 4;
            int gr = j0 + row; if (gr > Nc - 1) gr = Nc - 1;
            int gk = k0 + kq;
            int rem = K - gk;
            int bytes = rem >= 4 ? 16 : (rem > 0 ? rem * 4 : 0);
            const float* src = Bb + (size_t)gr * ldb + (bytes ? gk : 0);
            cpa16(Bs + row * 36 + kq, src, bytes);
        }
    } else {
        // B tile 32 x BN -> Bs[k][n], stride BN+8
#pragma unroll
        for (int l = 0; l < BN * 8 / NT; ++l) {
            int e = tid + l * NT;
            int kk = e / (BN / 4);
            int nq = (e % (BN / 4)) * 4;
            int gk = k0 + kk;
            int bytes = (gk < K) ? 16 : 0;
            const float* src = Bb + (size_t)(bytes ? gk : 0) * ldb + j0 + nq;
            cpa16(Bs + kk * (BN + 8) + nq, src, bytes);
        }
    }
}

template<int BN>
__global__ __launch_bounds__((BN == 256) ? 256 : 128, 1) void mma_gemm(
    const float* __restrict__ A, const float* __restrict__ Bm,
    const float* __restrict__ bias, float* __restrict__ C,
    int M, int Nc, int K, int lda, int ldb, int ldc,
    long long sA, long long sB, long long sC,
    float alpha, int transB, int relu)
{
    constexpr int ASZ = 128 * 36;
    constexpr int BSZ = (BN * 36 > 32 * (BN + 8)) ? BN * 36 : 32 * (BN + 8);
    constexpr int STG = ASZ + BSZ;

    extern __shared__ float sm[];

    const float* Ab = A  + (size_t)blockIdx.z * sA;
    const float* Bb = Bm + (size_t)blockIdx.z * sB;
    float*       Cb = C  + (size_t)blockIdx.z * sC;

    const int tid  = threadIdx.x;
    const int lane = tid & 31;
    const int wid  = tid >> 5;
    const int wr   = (wid & 1) * 64;
    const int wc   = (wid >> 1) * 64;
    const int g    = lane >> 2;
    const int t    = lane & 3;

    const int i0 = blockIdx.y * 128;
    const int j0 = blockIdx.x * BN;

    float acc[4][8][4];
#pragma unroll
    for (int mi = 0; mi < 4; ++mi)
#pragma unroll
        for (int ni = 0; ni < 8; ++ni)
#pragma unroll
            for (int q = 0; q < 4; ++q) acc[mi][ni][q] = 0.f;

    const int nk = (K + 31) / 32;

    // prologue: prefetch 2 chunks
#pragma unroll
    for (int s = 0; s < 2; ++s) {
        if (s < nk)
            load_chunk<BN>(sm + s * STG, sm + s * STG + ASZ, Ab, Bb,
                           i0, j0, M, Nc, K, lda, ldb, s * 32, tid, transB);
        cp_commit();
    }

    for (int c = 0; c < nk; ++c) {
        int pf = c + 2;
        if (pf < nk) {
            int st = pf % 3;
            load_chunk<BN>(sm + st * STG, sm + st * STG + ASZ, Ab, Bb,
                           i0, j0, M, Nc, K, lda, ldb, pf * 32, tid, transB);
        }
        cp_commit();
        cp_wait<2>();
        __syncthreads();

        const float* AsS = sm + (c % 3) * STG;
        const float* BsS = AsS + ASZ;

#pragma unroll
        for (int k8 = 0; k8 < 4; ++k8) {
            const int kb = k8 * 8;
            unsigned af[4][4];
#pragma unroll
            for (int mi = 0; mi < 4; ++mi) {
                int r = wr + mi * 16 + g;
                af[mi][0] = f2tf(AsS[(size_t)r * 36 + kb + t]);
                af[mi][1] = f2tf(AsS[(size_t)(r + 8) * 36 + kb + t]);
                af[mi][2] = f2tf(AsS[(size_t)r * 36 + kb + t + 4]);
                af[mi][3] = f2tf(AsS[(size_t)(r + 8) * 36 + kb + t + 4]);
            }
            unsigned bf[8][2];
            if (transB) {
#pragma unroll
                for (int ni = 0; ni < 8; ++ni) {
                    int cc = wc + ni * 8 + g;
                    bf[ni][0] = f2tf(BsS[(size_t)cc * 36 + kb + t]);
                    bf[ni][1] = f2tf(BsS[(size_t)cc * 36 + kb + t + 4]);
                }
            } else {
#pragma unroll
                for (int ni = 0; ni < 8; ++ni) {
                    int cc = wc + ni * 8 + g;
                    bf[ni][0] = f2tf(BsS[(size_t)(kb + t) * (BN + 8) + cc]);
                    bf[ni][1] = f2tf(BsS[(size_t)(kb + t + 4) * (BN + 8) + cc]);
                }
            }
#pragma unroll
            for (int mi = 0; mi < 4; ++mi)
#pragma unroll
                for (int ni = 0; ni < 8; ++ni)
                    mma_tf32(acc[mi][ni], af[mi], bf[ni]);
        }
        __syncthreads();
    }
    cp_wait<0>();

    // epilogue
#pragma unroll
    for (int mi = 0; mi < 4; ++mi) {
        int r0 = i0 + wr + mi * 16 + g;
#pragma unroll
        for (int ni = 0; ni < 8; ++ni) {
            int c0 = j0 + wc + ni * 8 + 2 * t;
            float b0v = 0.f, b1v = 0.f;
            if (bias) {
                if (c0 < Nc)     b0v = bias[c0];
                if (c0 + 1 < Nc) b1v = bias[c0 + 1];
            }
            float v00 = alpha * acc[mi][ni][0] + b0v;
            float v01 = alpha * acc[mi][ni][1] + b1v;
            float v10 = alpha * acc[mi][ni][2] + b0v;
            float v11 = alpha * acc[mi][ni][3] + b1v;
            if (relu) {
                v00 = fmaxf(v00, 0.f); v01 = fmaxf(v01, 0.f);
                v10 = fmaxf(v10, 0.f); v11 = fmaxf(v11, 0.f);
            }
            if (r0 < M) {
                if (c0 < Nc)     Cb[(size_t)r0 * ldc + c0]     = v00;
                if (c0 + 1 < Nc) Cb[(size_t)r0 * ldc + c0 + 1] = v01;
            }
            if (r0 + 8 < M) {
                if (c0 < Nc)     Cb[(size_t)(r0 + 8) * ldc + c0]     = v10;
                if (c0 + 1 < Nc) Cb[(size_t)(r0 + 8) * ldc + c0 + 1] = v11;
            }
        }
    }
}

// ---------------- elementwise kernels ----------------

__global__ void build_inp(const float* __restrict__ h, const float* __restrict__ embed,
                          const float* __restrict__ mlt) {
    int r = blockIdx.x, c = threadIdx.x;
    int b = r / N_, n = r % N_;
    g_s[(size_t)r * D_ + c] =
        h[((size_t)b * D_ + c) * N_ + n] + embed[(size_t)n * D_ + c] * mlt[(size_t)b * N_ + n];
}

__global__ void pad_adj(const float* __restrict__ adj) {
    int r = blockIdx.x, c = threadIdx.x;  // grid N_, block SCLD
    g_adjp[(size_t)r * SCLD + c] = (c < N_) ? adj[(size_t)r * N_ + c] : 0.f;
}

__global__ void softmax_rows(float* __restrict__ sc) {
    int row = blockIdx.x * 8 + threadIdx.y;
    float* p = sc + (size_t)row * SCLD;
    int lane = threadIdx.x;
    float mx = -1e30f;
    for (int j = lane; j < N_; j += 32) mx = fmaxf(mx, p[j]);
#pragma unroll
    for (int o = 16; o > 0; o >>= 1) mx = fmaxf(mx, __shfl_xor_sync(0xffffffffu, mx, o));
    float sum = 0.f;
    for (int j = lane; j < N_; j += 32) { float e = expf(p[j] - mx); p[j] = e; sum += e; }
#pragma unroll
    for (int o = 16; o > 0; o >>= 1) sum += __shfl_xor_sync(0xffffffffu, sum, o);
    float inv = 1.f / sum;
    for (int j = lane; j < N_; j += 32) p[j] *= inv;
}

__global__ void add_ln(const float* __restrict__ a, const float* __restrict__ bsrc,
                       const float* __restrict__ w, const float* __restrict__ bb,
                       float* __restrict__ outp) {
    int r = blockIdx.x, c = threadIdx.x;
    size_t idx = (size_t)r * D_ + c;
    float v = a[idx] + bsrc[idx];
    __shared__ float red[256];
    red[c] = v; __syncthreads();
#pragma unroll
    for (int s = 128; s > 0; s >>= 1) { if (c < s) red[c] += red[c + s]; __syncthreads(); }
    float mu = red[0] * (1.f / 256.f);
    __syncthreads();
    float dv = v - mu;
    red[c] = dv * dv; __syncthreads();
#pragma unroll
    for (int s = 128; s > 0; s >>= 1) { if (c < s) red[c] += red[c + s]; __syncthreads(); }
    float var = red[0] * (1.f / 256.f);
    outp[idx] = dv * rsqrtf(var + 1e-5f) * w[c] + bb[c];
}

__global__ void make_h_xg(const float* __restrict__ h, const float* __restrict__ x,
                          const float* __restrict__ dt, const int* __restrict__ step) {
    int r = blockIdx.x, c = threadIdx.x;
    int b = r / N_, n = r % N_;
    float hv = h[((size_t)b * D_ + c) * N_ + n];
    float hn;
    if (*step != 0) {
        float d = dt[b];
        hn = sqrtf(1.f - d) * hv - sqrtf(d) * tanhf(g_s3[(size_t)r * D_ + c]);
    } else {
        hn = hv;
    }
    g_hn[(size_t)r * D_ + c] = hn;
    g_z[(size_t)r * KC_ + DIN_ + c] = hn;
    if (c < DIN_)
        g_z[(size_t)r * KC_ + c] = x[((size_t)b * DIN_ + c) * N_ + n];
}

__global__ void final_combine(float* __restrict__ outp) {
    int b = blockIdx.z;
    int o0 = blockIdx.y * 32, n0 = blockIdx.x * 32;
    __shared__ float tbuf[32][33];
    int tx = threadIdx.x, ty = threadIdx.y;
#pragma unroll
    for (int s4 = 0; s4 < 4; ++s4) {
        int nl = ty + s4 * 8;
        int n = n0 + nl;
        float val = 0.f;
        if (n < N_) {
            size_t idx = ((size_t)(b * N_ + n)) * D_ + o0 + tx;
            float uu = 1.f / (1.f + expf(-g_gu[idx]));
            float cc = tanhf(g_gc[idx]);
            val = uu * g_hn[idx] + (1.f - uu) * cc;
        }
        tbuf[nl][tx] = val;
    }
    __syncthreads();
#pragma unroll
    for (int s4 = 0; s4 < 4; ++s4) {
        int ol = ty + s4 * 8;
        int n = n0 + tx;
        if (n < N_)
            outp[((size_t)(b * D_ + o0 + ol)) * N_ + n] = tbuf[tx][ol];
    }
}

// ---------------- launcher ----------------
extern "C" void kernel_launch(void* const* d_in, const int* in_sizes, int n_in,
                              void* d_out, int out_size) {
    const float* x          = (const float*)d_in[0];
    const float* delta_t    = (const float*)d_in[1];
    const float* h          = (const float*)d_in[2];
    const float* adj        = (const float*)d_in[3];
    const float* mlt        = (const float*)d_in[5];
    const int*   step       = (const int*)d_in[7];
    const float* embed      = (const float*)d_in[8];
    const float* in_proj_w  = (const float*)d_in[9];
    const float* in_proj_b  = (const float*)d_in[10];
    const float* out_proj_w = (const float*)d_in[11];
    const float* out_proj_b = (const float*)d_in[12];
    const float* ln1_w      = (const float*)d_in[13];
    const float* ln1_b      = (const float*)d_in[14];
    const float* ln2_w      = (const float*)d_in[15];
    const float* ln2_b      = (const float*)d_in[16];
    const float* ffn_w1     = (const float*)d_in[17];
    const float* ffn_b1     = (const float*)d_in[18];
    const float* ffn_w2     = (const float*)d_in[19];
    const float* ffn_b2     = (const float*)d_in[20];
    const float* W_u        = (const float*)d_in[21];
    const float* b_u        = (const float*)d_in[22];
    const float* W_c        = (const float*)d_in[23];
    const float* b_c        = (const float*)d_in[24];
    float* outp = (float*)d_out;

    void *vp;
    cudaGetSymbolAddress(&vp, g_s);    float* ps  = (float*)vp;
    cudaGetSymbolAddress(&vp, g_qkv);  float* pq  = (float*)vp;
    cudaGetSymbolAddress(&vp, g_sc);   float* psc = (float*)vp;
    cudaGetSymbolAddress(&vp, g_adjp); float* pad = (float*)vp;
    cudaGetSymbolAddress(&vp, g_o);    float* po  = (float*)vp;
    cudaGetSymbolAddress(&vp, g_s2);   float* ps2 = (float*)vp;
    cudaGetSymbolAddress(&vp, g_f1);   float* pf1 = (float*)vp;
    cudaGetSymbolAddress(&vp, g_s3);   float* ps3 = (float*)vp;
    cudaGetSymbolAddress(&vp, g_z);    float* pz  = (float*)vp;
    cudaGetSymbolAddress(&vp, g_gu);   float* pgu = (float*)vp;
    cudaGetSymbolAddress(&vp, g_gc);   float* pgc = (float*)vp;

    static const int SM256 = 3 * (128 * 36 + 256 * 36) * 4;      // 165888
    static const int SM128 = 3 * (128 * 36 + 128 * 36) * 4;      // 110592
    cudaFuncSetAttribute(mma_gemm<256>, cudaFuncAttributeMaxDynamicSharedMemorySize, SM256);
    cudaFuncSetAttribute(mma_gemm<128>, cudaFuncAttributeMaxDynamicSharedMemorySize, SM128);

    // 0. pad adj to aligned lda
    pad_adj<<<N_, SCLD>>>(adj);

    // 1. transformer input
    build_inp<<<NB_, 256>>>(h, embed, mlt);

    // 2. QKV: (NB x 256) @ (768 x 256)^T + bias
    mma_gemm<256><<<dim3(3, 414, 1), 256, SM256>>>(ps, in_proj_w, in_proj_b, pq,
        NB_, QKVLD, 256, 256, 256, QKVLD, 0, 0, 0, 1.f, 1, 0);

    // 3. scores: per-batch Q @ K^T / 16 (ldc padded to 208)
    mma_gemm<256><<<dim3(1, 2, B_), 256, SM256>>>(pq, pq + 256, nullptr, psc,
        N_, N_, 256, QKVLD, QKVLD, SCLD,
        (long long)N_ * QKVLD, (long long)N_ * QKVLD, (long long)N_ * SCLD,
        1.f / 16.f, 1, 0);

    // 4. softmax
    softmax_rows<<<NB_ / 8, dim3(32, 8)>>>(psc);

    // 5. attn @ V (NN), A lda=208 aligned
    mma_gemm<256><<<dim3(1, 2, B_), 256, SM256>>>(psc, pq + 512, nullptr, po,
        N_, 256, N_, SCLD, QKVLD, 256,
        (long long)N_ * SCLD, (long long)N_ * QKVLD, (long long)N_ * 256,
        1.f, 0, 0);

    // 6. out projection
    mma_gemm<256><<<dim3(1, 414, 1), 256, SM256>>>(po, out_proj_w, out_proj_b, pf1,
        NB_, 256, 256, 256, 256, 256, 0, 0, 0, 1.f, 1, 0);

    // 7. LN1
    add_ln<<<NB_, 256>>>(ps, pf1, ln1_w, ln1_b, ps2);

    // 8. FFN
    mma_gemm<256><<<dim3(1, 414, 1), 256, SM256>>>(ps2, ffn_w1, ffn_b1, po,
        NB_, 256, 256, 256, 256, 256, 0, 0, 0, 1.f, 1, 1);
    mma_gemm<256><<<dim3(1, 414, 1), 256, SM256>>>(po, ffn_w2, ffn_b2, pf1,
        NB_, 256, 256, 256, 256, 256, 0, 0, 0, 1.f, 1, 0);

    // 9. LN2
    add_ln<<<NB_, 256>>>(ps2, pf1, ln2_w, ln2_b, ps3);

    // 10. h update + z block 0
    make_h_xg<<<NB_, 256>>>(h, x, delta_t, step);

    // 11. diffusion: z_k = adj @ z_{k-1} per batch (NN), padded adj lda=208
    for (int k = 1; k <= 3; ++k) {
        mma_gemm<128><<<dim3(3, 2, B_), 128, SM128>>>(pad, pz + (size_t)(k - 1) * CXG_,
            nullptr, pz + (size_t)k * CXG_,
            N_, CXG_, N_, SCLD, KC_, KC_,
            0LL, (long long)N_ * KC_, (long long)N_ * KC_,
            1.f, 0, 0);
    }

    // 12. gates: (NB x 1280) @ (256 x 1280)^T + bias
    mma_gemm<256><<<dim3(1, 414, 1), 256, SM256>>>(pz, W_u, b_u, pgu,
        NB_, 256, KC_, KC_, KC_, 256, 0, 0, 0, 1.f, 1, 0);
    mma_gemm<256><<<dim3(1, 414, 1), 256, SM256>>>(pz, W_c, b_c, pgc,
        NB_, 256, KC_, KC_, KC_, 256, 0, 0, 0, 1.f, 1, 0);

    // 13. gated combine + transpose
    final_combine<<<dim3(7, 8, B_), dim3(32, 8)>>>(outp);
}

// round 4
// speedup vs baseline: 2.9910x; 1.1390x over previous
#include <cuda_runtime.h>
#include <math.h>

// Problem constants
#define B_    256
#define N_    207
#define D_    256
#define DIN_  64
#define CXG_  320
#define KC_   1280
#define NB_   52992
#define QKVLD 768
#define SCLD  208

// ---------------- scratch ----------------
__device__ float g_s   [(size_t)NB_ * D_];
__device__ float g_qkv [(size_t)NB_ * QKVLD];
__device__ float g_sc  [(size_t)B_ * N_ * SCLD + 256];
__device__ float g_adjp[(size_t)N_ * SCLD];
__device__ float g_o   [(size_t)NB_ * D_];
__device__ float g_s2  [(size_t)NB_ * D_];
__device__ float g_f1  [(size_t)NB_ * D_];
__device__ float g_hn  [(size_t)NB_ * D_];
__device__ float g_z   [(size_t)NB_ * KC_];
__device__ float g_guc [(size_t)NB_ * 512];   // [u | c] pre-activations
__device__ float g_wuc [(size_t)512 * KC_];   // [W_u ; W_c]
__device__ float g_buc [512];

// ---------------- helpers ----------------
__device__ __forceinline__ void mma_tf32(float* c, const unsigned* a, const unsigned* b) {
    asm volatile(
        "mma.sync.aligned.m16n8k8.row.col.f32.tf32.tf32.f32 "
        "{%0,%1,%2,%3}, {%4,%5,%6,%7}, {%8,%9}, {%0,%1,%2,%3};\n"
        : "+f"(c[0]), "+f"(c[1]), "+f"(c[2]), "+f"(c[3])
        : "r"(a[0]), "r"(a[1]), "r"(a[2]), "r"(a[3]), "r"(b[0]), "r"(b[1]));
}

__device__ __forceinline__ void cpa16(float* dst, const float* src, int srcbytes) {
    unsigned d = (unsigned)__cvta_generic_to_shared(dst);
    asm volatile("cp.async.cg.shared.global [%0], [%1], 16, %2;\n"
                 :: "r"(d), "l"(src), "r"(srcbytes));
}
__device__ __forceinline__ void cp_commit() {
    asm volatile("cp.async.commit_group;\n" ::: "memory");
}
template <int NGRP>
__device__ __forceinline__ void cp_wait() {
    asm volatile("cp.async.wait_group %0;\n" :: "n"(NGRP) : "memory");
}

// ---------------- TF32 tensor-core GEMM ----------------
// C = alpha * A @ op(B) + bias, optional relu. transB: B is Nc x K row-major;
// else B is K x Nc row-major. Batched via blockIdx.z with strides.
// BM=128, BN in {256 (8 warps, 1 CTA/SM), 128 (4 warps, 2 CTA/SM)}, BK=32,
// warp tile 64x64, NST-stage cp.async pipeline. lda/ldb must be %4==0.
// fp32 bits fed raw to TF32 HMMA (HW truncates mantissa).
template<int BN>
__device__ __forceinline__ void load_chunk(
    float* As, float* Bs, const float* Ab, const float* Bb,
    int i0, int j0, int M, int Nc, int K, int lda, int ldb,
    int k0, int tid, int transB)
{
    constexpr int NT = (BN == 256) ? 256 : 128;
#pragma unroll
    for (int l = 0; l < 1024 / NT; ++l) {
        int e = tid + l * NT;
        int row = e >> 3, kq = (e & 7) * 4;
        int gr = i0 + row; if (gr > M - 1) gr = M - 1;
        int gk = k0 + kq;
        int rem = K - gk;
        int bytes = rem >= 4 ? 16 : (rem > 0 ? rem * 4 : 0);
        const float* src = Ab + (size_t)gr * lda + (bytes ? gk : 0);
        cpa16(As + row * 36 + kq, src, bytes);
    }
    if (transB) {
#pragma unroll
        for (int l = 0; l < BN * 8 / NT; ++l) {
            int e = tid + l * NT;
            int row = e >> 3, kq = (e & 7) * 4;
            int gr = j0 + row; if (gr > Nc - 1) gr = Nc - 1;
            int gk = k0 + kq;
            int rem = K - gk;
            int bytes = rem >= 4 ? 16 : (rem > 0 ? rem * 4 : 0);
            const float* src = Bb + (size_t)gr * ldb + (bytes ? gk : 0);
            cpa16(Bs + row * 36 + kq, src, bytes);
        }
    } else {
#pragma unroll
        for (int l = 0; l < BN * 8 / NT; ++l) {
            int e = tid + l * NT;
            int kk = e / (BN / 4);
            int nq = (e % (BN / 4)) * 4;
            int gk = k0 + kk;
            int bytes = (gk < K) ? 16 : 0;
            const float* src = Bb + (size_t)(bytes ? gk : 0) * ldb + j0 + nq;
            cpa16(Bs + kk * (BN + 8) + nq, src, bytes);
        }
    }
}

template<int BN, int NST>
__global__ __launch_bounds__((BN == 256) ? 256 : 128, (BN == 256) ? 1 : 2)
void mma_gemm(
    const float* __restrict__ A, const float* __restrict__ Bm,
    const float* __restrict__ bias, float* __restrict__ C,
    int M, int Nc, int K, int lda, int ldb, int ldc,
    long long sA, long long sB, long long sC,
    float alpha, int transB, int relu)
{
    constexpr int ASZ = 128 * 36;
    constexpr int BSZ = (BN * 36 > 32 * (BN + 8)) ? BN * 36 : 32 * (BN + 8);
    constexpr int STG = ASZ + BSZ;

    extern __shared__ float sm[];

    const float* Ab = A  + (size_t)blockIdx.z * sA;
    const float* Bb = Bm + (size_t)blockIdx.z * sB;
    float*       Cb = C  + (size_t)blockIdx.z * sC;

    const int tid  = threadIdx.x;
    const int lane = tid & 31;
    const int wid  = tid >> 5;
    const int wr   = (wid & 1) * 64;
    const int wc   = (wid >> 1) * 64;
    const int g    = lane >> 2;
    const int t    = lane & 3;

    const int i0 = blockIdx.y * 128;
    const int j0 = blockIdx.x * BN;

    float acc[4][8][4];
#pragma unroll
    for (int mi = 0; mi < 4; ++mi)
#pragma unroll
        for (int ni = 0; ni < 8; ++ni)
#pragma unroll
            for (int q = 0; q < 4; ++q) acc[mi][ni][q] = 0.f;

    const int nk = (K + 31) / 32;

#pragma unroll
    for (int s = 0; s < NST - 1; ++s) {
        if (s < nk)
            load_chunk<BN>(sm + s * STG, sm + s * STG + ASZ, Ab, Bb,
                           i0, j0, M, Nc, K, lda, ldb, s * 32, tid, transB);
        cp_commit();
    }

    for (int c = 0; c < nk; ++c) {
        int pf = c + NST - 1;
        if (pf < nk) {
            int st = pf % NST;
            load_chunk<BN>(sm + st * STG, sm + st * STG + ASZ, Ab, Bb,
                           i0, j0, M, Nc, K, lda, ldb, pf * 32, tid, transB);
        }
        cp_commit();
        cp_wait<NST - 1>();
        __syncthreads();

        const unsigned* AsU = (const unsigned*)(sm + (c % NST) * STG);
        const unsigned* BsU = AsU + ASZ;

#pragma unroll
        for (int k8 = 0; k8 < 4; ++k8) {
            const int kb = k8 * 8;
            unsigned af[4][4];
#pragma unroll
            for (int mi = 0; mi < 4; ++mi) {
                int r = wr + mi * 16 + g;
                af[mi][0] = AsU[(size_t)r * 36 + kb + t];
                af[mi][1] = AsU[(size_t)(r + 8) * 36 + kb + t];
                af[mi][2] = AsU[(size_t)r * 36 + kb + t + 4];
                af[mi][3] = AsU[(size_t)(r + 8) * 36 + kb + t + 4];
            }
            unsigned bf[8][2];
            if (transB) {
#pragma unroll
                for (int ni = 0; ni < 8; ++ni) {
                    int cc = wc + ni * 8 + g;
                    bf[ni][0] = BsU[(size_t)cc * 36 + kb + t];
                    bf[ni][1] = BsU[(size_t)cc * 36 + kb + t + 4];
                }
            } else {
#pragma unroll
                for (int ni = 0; ni < 8; ++ni) {
                    int cc = wc + ni * 8 + g;
                    bf[ni][0] = BsU[(size_t)(kb + t) * (BN + 8) + cc];
                    bf[ni][1] = BsU[(size_t)(kb + t + 4) * (BN + 8) + cc];
                }
            }
#pragma unroll
            for (int mi = 0; mi < 4; ++mi)
#pragma unroll
                for (int ni = 0; ni < 8; ++ni)
                    mma_tf32(acc[mi][ni], af[mi], bf[ni]);
        }
        __syncthreads();
    }
    cp_wait<0>();

#pragma unroll
    for (int mi = 0; mi < 4; ++mi) {
        int r0 = i0 + wr + mi * 16 + g;
#pragma unroll
        for (int ni = 0; ni < 8; ++ni) {
            int c0 = j0 + wc + ni * 8 + 2 * t;
            float b0v = 0.f, b1v = 0.f;
            if (bias) {
                if (c0 < Nc)     b0v = bias[c0];
                if (c0 + 1 < Nc) b1v = bias[c0 + 1];
            }
            float v00 = alpha * acc[mi][ni][0] + b0v;
            float v01 = alpha * acc[mi][ni][1] + b1v;
            float v10 = alpha * acc[mi][ni][2] + b0v;
            float v11 = alpha * acc[mi][ni][3] + b1v;
            if (relu) {
                v00 = fmaxf(v00, 0.f); v01 = fmaxf(v01, 0.f);
                v10 = fmaxf(v10, 0.f); v11 = fmaxf(v11, 0.f);
            }
            if (r0 < M) {
                if (c0 < Nc)     Cb[(size_t)r0 * ldc + c0]     = v00;
                if (c0 + 1 < Nc) Cb[(size_t)r0 * ldc + c0 + 1] = v01;
            }
            if (r0 + 8 < M) {
                if (c0 < Nc)     Cb[(size_t)(r0 + 8) * ldc + c0]     = v10;
                if (c0 + 1 < Nc) Cb[(size_t)(r0 + 8) * ldc + c0 + 1] = v11;
            }
        }
    }
}

// ---------------- elementwise kernels ----------------

__global__ void build_inp(const float* __restrict__ h, const float* __restrict__ embed,
                          const float* __restrict__ mlt) {
    int r = blockIdx.x, c = threadIdx.x;
    int b = r / N_, n = r % N_;
    g_s[(size_t)r * D_ + c] =
        h[((size_t)b * D_ + c) * N_ + n] + embed[(size_t)n * D_ + c] * mlt[(size_t)b * N_ + n];
}

__global__ void pad_adj(const float* __restrict__ adj) {
    int r = blockIdx.x, c = threadIdx.x;
    g_adjp[(size_t)r * SCLD + c] = (c < N_) ? adj[(size_t)r * N_ + c] : 0.f;
}

__global__ void concat_w(const float* __restrict__ Wu, const float* __restrict__ Wc) {
    int row = blockIdx.x, c = threadIdx.x;  // grid 512, block 256
#pragma unroll
    for (int l = 0; l < 5; ++l) {
        int k = c + l * 256;
        g_wuc[(size_t)row * KC_ + k] =
            (row < 256) ? Wu[(size_t)row * KC_ + k] : Wc[(size_t)(row - 256) * KC_ + k];
    }
}
__global__ void concat_b(const float* __restrict__ bu, const float* __restrict__ bc) {
    int o = threadIdx.x;  // block 512
    g_buc[o] = (o < 256) ? bu[o] : bc[o - 256];
}

__global__ void softmax_rows(float* __restrict__ sc) {
    int row = blockIdx.x * 8 + threadIdx.y;
    float* p = sc + (size_t)row * SCLD;
    int lane = threadIdx.x;
    float mx = -1e30f;
    for (int j = lane; j < N_; j += 32) mx = fmaxf(mx, p[j]);
#pragma unroll
    for (int o = 16; o > 0; o >>= 1) mx = fmaxf(mx, __shfl_xor_sync(0xffffffffu, mx, o));
    float sum = 0.f;
    for (int j = lane; j < N_; j += 32) { float e = expf(p[j] - mx); p[j] = e; sum += e; }
#pragma unroll
    for (int o = 16; o > 0; o >>= 1) sum += __shfl_xor_sync(0xffffffffu, sum, o);
    float inv = 1.f / sum;
    for (int j = lane; j < N_; j += 32) p[j] *= inv;
}

__global__ void add_ln(const float* __restrict__ a, const float* __restrict__ bsrc,
                       const float* __restrict__ w, const float* __restrict__ bb,
                       float* __restrict__ outp) {
    int r = blockIdx.x, c = threadIdx.x;
    size_t idx = (size_t)r * D_ + c;
    float v = a[idx] + bsrc[idx];
    __shared__ float red[256];
    red[c] = v; __syncthreads();
#pragma unroll
    for (int s = 128; s > 0; s >>= 1) { if (c < s) red[c] += red[c + s]; __syncthreads(); }
    float mu = red[0] * (1.f / 256.f);
    __syncthreads();
    float dv = v - mu;
    red[c] = dv * dv; __syncthreads();
#pragma unroll
    for (int s = 128; s > 0; s >>= 1) { if (c < s) red[c] += red[c + s]; __syncthreads(); }
    float var = red[0] * (1.f / 256.f);
    outp[idx] = dv * rsqrtf(var + 1e-5f) * w[c] + bb[c];
}

// LN2(s2 + f1) -> tanh -> h update -> write g_hn and z block 0 (fused)
__global__ void ln2_make_h_xg(const float* __restrict__ a, const float* __restrict__ bsrc,
                              const float* __restrict__ w, const float* __restrict__ bb,
                              const float* __restrict__ h, const float* __restrict__ x,
                              const float* __restrict__ dt, const int* __restrict__ step) {
    int r = blockIdx.x, c = threadIdx.x;
    int b = r / N_, n = r % N_;
    size_t idx = (size_t)r * D_ + c;
    float v = a[idx] + bsrc[idx];
    __shared__ float red[256];
    red[c] = v; __syncthreads();
#pragma unroll
    for (int s = 128; s > 0; s >>= 1) { if (c < s) red[c] += red[c + s]; __syncthreads(); }
    float mu = red[0] * (1.f / 256.f);
    __syncthreads();
    float dv = v - mu;
    red[c] = dv * dv; __syncthreads();
#pragma unroll
    for (int s = 128; s > 0; s >>= 1) { if (c < s) red[c] += red[c + s]; __syncthreads(); }
    float var = red[0] * (1.f / 256.f);
    float s3v = dv * rsqrtf(var + 1e-5f) * w[c] + bb[c];

    float hv = h[((size_t)b * D_ + c) * N_ + n];
    float hn;
    if (*step != 0) {
        float d = dt[b];
        hn = sqrtf(1.f - d) * hv - sqrtf(d) * tanhf(s3v);
    } else {
        hn = hv;
    }
    g_hn[idx] = hn;
    g_z[(size_t)r * KC_ + DIN_ + c] = hn;
    if (c < DIN_)
        g_z[(size_t)r * KC_ + c] = x[((size_t)b * DIN_ + c) * N_ + n];
}

__global__ void final_combine(float* __restrict__ outp) {
    int b = blockIdx.z;
    int o0 = blockIdx.y * 32, n0 = blockIdx.x * 32;
    __shared__ float tbuf[32][33];
    int tx = threadIdx.x, ty = threadIdx.y;
#pragma unroll
    for (int s4 = 0; s4 < 4; ++s4) {
        int nl = ty + s4 * 8;
        int n = n0 + nl;
        float val = 0.f;
        if (n < N_) {
            size_t r = (size_t)(b * N_ + n);
            float gu = g_guc[r * 512 + o0 + tx];
            float gc = g_guc[r * 512 + 256 + o0 + tx];
            float uu = 1.f / (1.f + expf(-gu));
            float cc = tanhf(gc);
            val = uu * g_hn[r * D_ + o0 + tx] + (1.f - uu) * cc;
        }
        tbuf[nl][tx] = val;
    }
    __syncthreads();
#pragma unroll
    for (int s4 = 0; s4 < 4; ++s4) {
        int ol = ty + s4 * 8;
        int n = n0 + tx;
        if (n < N_)
            outp[((size_t)(b * D_ + o0 + ol)) * N_ + n] = tbuf[tx][ol];
    }
}

// ---------------- launcher ----------------
extern "C" void kernel_launch(void* const* d_in, const int* in_sizes, int n_in,
                              void* d_out, int out_size) {
    const float* x          = (const float*)d_in[0];
    const float* delta_t    = (const float*)d_in[1];
    const float* h          = (const float*)d_in[2];
    const float* adj        = (const float*)d_in[3];
    const float* mlt        = (const float*)d_in[5];
    const int*   step       = (const int*)d_in[7];
    const float* embed      = (const float*)d_in[8];
    const float* in_proj_w  = (const float*)d_in[9];
    const float* in_proj_b  = (const float*)d_in[10];
    const float* out_proj_w = (const float*)d_in[11];
    const float* out_proj_b = (const float*)d_in[12];
    const float* ln1_w      = (const float*)d_in[13];
    const float* ln1_b      = (const float*)d_in[14];
    const float* ln2_w      = (const float*)d_in[15];
    const float* ln2_b      = (const float*)d_in[16];
    const float* ffn_w1     = (const float*)d_in[17];
    const float* ffn_b1     = (const float*)d_in[18];
    const float* ffn_w2     = (const float*)d_in[19];
    const float* ffn_b2     = (const float*)d_in[20];
    const float* W_u        = (const float*)d_in[21];
    const float* b_u        = (const float*)d_in[22];
    const float* W_c        = (const float*)d_in[23];
    const float* b_c        = (const float*)d_in[24];
    float* outp = (float*)d_out;

    void *vp;
    cudaGetSymbolAddress(&vp, g_s);    float* ps   = (float*)vp;
    cudaGetSymbolAddress(&vp, g_qkv);  float* pq   = (float*)vp;
    cudaGetSymbolAddress(&vp, g_sc);   float* psc  = (float*)vp;
    cudaGetSymbolAddress(&vp, g_adjp); float* padj = (float*)vp;
    cudaGetSymbolAddress(&vp, g_o);    float* po   = (float*)vp;
    cudaGetSymbolAddress(&vp, g_s2);   float* ps2  = (float*)vp;
    cudaGetSymbolAddress(&vp, g_f1);   float* pf1  = (float*)vp;
    cudaGetSymbolAddress(&vp, g_z);    float* pz   = (float*)vp;
    cudaGetSymbolAddress(&vp, g_guc);  float* pguc = (float*)vp;
    cudaGetSymbolAddress(&vp, g_wuc);  float* pwuc = (float*)vp;
    cudaGetSymbolAddress(&vp, g_buc);  float* pbuc = (float*)vp;

    static const int SM256 = 3 * (128 * 36 + 256 * 36) * 4;   // 165888
    static const int SM128 = 2 * (128 * 36 + 128 * 36) * 4;   // 73728
    cudaFuncSetAttribute(mma_gemm<256, 3>, cudaFuncAttributeMaxDynamicSharedMemorySize, SM256);
    cudaFuncSetAttribute(mma_gemm<128, 2>, cudaFuncAttributeMaxDynamicSharedMemorySize, SM128);

    // 0. prep: pad adj, concat gate weights
    pad_adj<<<N_, SCLD>>>(adj);
    concat_w<<<512, 256>>>(W_u, W_c);
    concat_b<<<1, 512>>>(b_u, b_c);

    // 1. transformer input
    build_inp<<<NB_, 256>>>(h, embed, mlt);

    // 2. QKV
    mma_gemm<256, 3><<<dim3(3, 414, 1), 256, SM256>>>(ps, in_proj_w, in_proj_b, pq,
        NB_, QKVLD, 256, 256, 256, QKVLD, 0, 0, 0, 1.f, 1, 0);

    // 3. scores: per-batch Q @ K^T / 16 (ldc = 208)
    mma_gemm<256, 3><<<dim3(1, 2, B_), 256, SM256>>>(pq, pq + 256, nullptr, psc,
        N_, N_, 256, QKVLD, QKVLD, SCLD,
        (long long)N_ * QKVLD, (long long)N_ * QKVLD, (long long)N_ * SCLD,
        1.f / 16.f, 1, 0);

    // 4. softmax
    softmax_rows<<<NB_ / 8, dim3(32, 8)>>>(psc);

    // 5. attn @ V (NN)
    mma_gemm<256, 3><<<dim3(1, 2, B_), 256, SM256>>>(psc, pq + 512, nullptr, po,
        N_, 256, N_, SCLD, QKVLD, 256,
        (long long)N_ * SCLD, (long long)N_ * QKVLD, (long long)N_ * 256,
        1.f, 0, 0);

    // 6. out projection
    mma_gemm<256, 3><<<dim3(1, 414, 1), 256, SM256>>>(po, out_proj_w, out_proj_b, pf1,
        NB_, 256, 256, 256, 256, 256, 0, 0, 0, 1.f, 1, 0);

    // 7. LN1
    add_ln<<<NB_, 256>>>(ps, pf1, ln1_w, ln1_b, ps2);

    // 8. FFN
    mma_gemm<256, 3><<<dim3(1, 414, 1), 256, SM256>>>(ps2, ffn_w1, ffn_b1, po,
        NB_, 256, 256, 256, 256, 256, 0, 0, 0, 1.f, 1, 1);
    mma_gemm<256, 3><<<dim3(1, 414, 1), 256, SM256>>>(po, ffn_w2, ffn_b2, pf1,
        NB_, 256, 256, 256, 256, 256, 0, 0, 0, 1.f, 1, 0);

    // 9+10. LN2 + h update + z block 0 (fused)
    ln2_make_h_xg<<<NB_, 256>>>(ps2, pf1, ln2_w, ln2_b, h, x, delta_t, step);

    // 11. diffusion: z_k = adj @ z_{k-1} per batch (NN)
    for (int k = 1; k <= 3; ++k) {
        mma_gemm<128, 2><<<dim3(3, 2, B_), 128, SM128>>>(padj, pz + (size_t)(k - 1) * CXG_,
            nullptr, pz + (size_t)k * CXG_,
            N_, CXG_, N_, SCLD, KC_, KC_,
            0LL, (long long)N_ * KC_, (long long)N_ * KC_,
            1.f, 0, 0);
    }

    // 12. fused gates: (NB x 1280) @ (512 x 1280)^T + bias
    mma_gemm<256, 3><<<dim3(2, 414, 1), 256, SM256>>>(pz, pwuc, pbuc, pguc,
        NB_, 512, KC_, KC_, KC_, 512, 0, 0, 0, 1.f, 1, 0);

    // 13. gated combine + transpose
    final_combine<<<dim3(7, 8, B_), dim3(32, 8)>>>(outp);
}

// round 5
// speedup vs baseline: 3.2271x; 1.0789x over previous
#include <cuda_runtime.h>
#include <math.h>

// Problem constants
#define B_    256
#define N_    207
#define D_    256
#define DIN_  64
#define CXG_  320
#define KC_   1280
#define NB_   52992
#define QKVLD 768
#define SCLD  208
#define ZROW  81920            // B_ * CXG_  (diffusion matrix row stride)
#define ZK    ((size_t)NB_ * CXG_)   // floats per diffusion order

// ---------------- scratch ----------------
__device__ float g_s   [(size_t)NB_ * D_];
__device__ float g_qkv [(size_t)NB_ * QKVLD];
__device__ float g_sc  [(size_t)B_ * N_ * SCLD + 256];
__device__ float g_adjp[(size_t)N_ * SCLD];
__device__ float g_o   [(size_t)NB_ * D_];
__device__ float g_s2  [(size_t)NB_ * D_];
__device__ float g_f1  [(size_t)NB_ * D_];
__device__ float g_hn  [(size_t)NB_ * D_];
__device__ float g_z   [4 * ZK];              // [k][n][b][c]
__device__ float g_guc [(size_t)NB_ * 512];   // rows r' = n*B+b, [u | c]
__device__ float g_wuc [(size_t)512 * KC_];
__device__ float g_buc [512];

// ---------------- helpers ----------------
__device__ __forceinline__ void mma_tf32(float* c, const unsigned* a, const unsigned* b) {
    asm volatile(
        "mma.sync.aligned.m16n8k8.row.col.f32.tf32.tf32.f32 "
        "{%0,%1,%2,%3}, {%4,%5,%6,%7}, {%8,%9}, {%0,%1,%2,%3};\n"
        : "+f"(c[0]), "+f"(c[1]), "+f"(c[2]), "+f"(c[3])
        : "r"(a[0]), "r"(a[1]), "r"(a[2]), "r"(a[3]), "r"(b[0]), "r"(b[1]));
}

__device__ __forceinline__ void cpa16(float* dst, const float* src, int srcbytes) {
    unsigned d = (unsigned)__cvta_generic_to_shared(dst);
    asm volatile("cp.async.cg.shared.global [%0], [%1], 16, %2;\n"
                 :: "r"(d), "l"(src), "r"(srcbytes));
}
__device__ __forceinline__ void cp_commit() {
    asm volatile("cp.async.commit_group;\n" ::: "memory");
}
template <int NGRP>
__device__ __forceinline__ void cp_wait() {
    asm volatile("cp.async.wait_group %0;\n" :: "n"(NGRP) : "memory");
}

// ---------------- TF32 tensor-core GEMM ----------------
// C = alpha * A @ op(B) + bias, optional relu. transB: B is Nc x K row-major;
// else B is K x Nc row-major. Batched via blockIdx.z.
// A may have a blocked K layout: columns [kb*aksub, (kb+1)*aksub) live at
// A + kb*akstr extra offset (akstr = block stride - aksub). Chunks (32) never
// straddle blocks when aksub % 32 == 0.
template<int BN>
__device__ __forceinline__ void load_chunk(
    float* As, float* Bs, const float* Ab, const float* Bb,
    int i0, int j0, int M, int Nc, int K, int lda, int ldb,
    int k0, int tid, int transB)
{
    constexpr int NT = 256;
#pragma unroll
    for (int l = 0; l < 1024 / NT; ++l) {
        int e = tid + l * NT;
        int row = e >> 3, kq = (e & 7) * 4;
        int gr = i0 + row; if (gr > M - 1) gr = M - 1;
        int gk = k0 + kq;
        int rem = K - gk;
        int bytes = rem >= 4 ? 16 : (rem > 0 ? rem * 4 : 0);
        const float* src = Ab + (size_t)gr * lda + (bytes ? gk : 0);
        cpa16(As + row * 36 + kq, src, bytes);
    }
    if (transB) {
#pragma unroll
        for (int l = 0; l < BN * 8 / NT; ++l) {
            int e = tid + l * NT;
            int row = e >> 3, kq = (e & 7) * 4;
            int gr = j0 + row; if (gr > Nc - 1) gr = Nc - 1;
            int gk = k0 + kq;
            int rem = K - gk;
            int bytes = rem >= 4 ? 16 : (rem > 0 ? rem * 4 : 0);
            const float* src = Bb + (size_t)gr * ldb + (bytes ? gk : 0);
            cpa16(Bs + row * 36 + kq, src, bytes);
        }
    } else {
#pragma unroll
        for (int l = 0; l < BN * 8 / NT; ++l) {
            int e = tid + l * NT;
            int kk = e / (BN / 4);
            int nq = (e % (BN / 4)) * 4;
            int gk = k0 + kk;
            int bytes = (gk < K) ? 16 : 0;
            const float* src = Bb + (size_t)(bytes ? gk : 0) * ldb + j0 + nq;
            cpa16(Bs + kk * (BN + 8) + nq, src, bytes);
        }
    }
}

template<int BN, int NST>
__global__ __launch_bounds__(256, 1)
void mma_gemm(
    const float* __restrict__ A, const float* __restrict__ Bm,
    const float* __restrict__ bias, float* __restrict__ C,
    int M, int Nc, int K, int lda, int ldb, int ldc,
    long long sA, long long sB, long long sC,
    float alpha, int transB, int relu,
    int aksub, long long akstr)
{
    constexpr int ASZ = 128 * 36;
    constexpr int BSZ = (BN * 36 > 32 * (BN + 8)) ? BN * 36 : 32 * (BN + 8);
    constexpr int STG = ASZ + BSZ;

    extern __shared__ float sm[];

    const float* Ab = A  + (size_t)blockIdx.z * sA;
    const float* Bb = Bm + (size_t)blockIdx.z * sB;
    float*       Cb = C  + (size_t)blockIdx.z * sC;

    const int tid  = threadIdx.x;
    const int lane = tid & 31;
    const int wid  = tid >> 5;
    const int wr   = (wid & 1) * 64;
    const int wc   = (wid >> 1) * 64;
    const int g    = lane >> 2;
    const int t    = lane & 3;

    const int i0 = blockIdx.y * 128;
    const int j0 = blockIdx.x * BN;

    float acc[4][8][4];
#pragma unroll
    for (int mi = 0; mi < 4; ++mi)
#pragma unroll
        for (int ni = 0; ni < 8; ++ni)
#pragma unroll
            for (int q = 0; q < 4; ++q) acc[mi][ni][q] = 0.f;

    const int nk = (K + 31) / 32;

#pragma unroll
    for (int s = 0; s < NST - 1; ++s) {
        if (s < nk) {
            const float* AbC = Ab + (aksub ? (long long)((s * 32) / aksub) * akstr : 0);
            load_chunk<BN>(sm + s * STG, sm + s * STG + ASZ, AbC, Bb,
                           i0, j0, M, Nc, K, lda, ldb, s * 32, tid, transB);
        }
        cp_commit();
    }

    for (int c = 0; c < nk; ++c) {
        int pf = c + NST - 1;
        if (pf < nk) {
            int st = pf % NST;
            const float* AbC = Ab + (aksub ? (long long)((pf * 32) / aksub) * akstr : 0);
            load_chunk<BN>(sm + st * STG, sm + st * STG + ASZ, AbC, Bb,
                           i0, j0, M, Nc, K, lda, ldb, pf * 32, tid, transB);
        }
        cp_commit();
        cp_wait<NST - 1>();
        __syncthreads();

        const unsigned* AsU = (const unsigned*)(sm + (c % NST) * STG);
        const unsigned* BsU = AsU + ASZ;

#pragma unroll
        for (int k8 = 0; k8 < 4; ++k8) {
            const int kb = k8 * 8;
            unsigned af[4][4];
#pragma unroll
            for (int mi = 0; mi < 4; ++mi) {
                int r = wr + mi * 16 + g;
                af[mi][0] = AsU[(size_t)r * 36 + kb + t];
                af[mi][1] = AsU[(size_t)(r + 8) * 36 + kb + t];
                af[mi][2] = AsU[(size_t)r * 36 + kb + t + 4];
                af[mi][3] = AsU[(size_t)(r + 8) * 36 + kb + t + 4];
            }
            unsigned bf[8][2];
            if (transB) {
#pragma unroll
                for (int ni = 0; ni < 8; ++ni) {
                    int cc = wc + ni * 8 + g;
                    bf[ni][0] = BsU[(size_t)cc * 36 + kb + t];
                    bf[ni][1] = BsU[(size_t)cc * 36 + kb + t + 4];
                }
            } else {
#pragma unroll
                for (int ni = 0; ni < 8; ++ni) {
                    int cc = wc + ni * 8 + g;
                    bf[ni][0] = BsU[(size_t)(kb + t) * (BN + 8) + cc];
                    bf[ni][1] = BsU[(size_t)(kb + t + 4) * (BN + 8) + cc];
                }
            }
#pragma unroll
            for (int mi = 0; mi < 4; ++mi)
#pragma unroll
                for (int ni = 0; ni < 8; ++ni)
                    mma_tf32(acc[mi][ni], af[mi], bf[ni]);
        }
        __syncthreads();
    }
    cp_wait<0>();

#pragma unroll
    for (int mi = 0; mi < 4; ++mi) {
        int r0 = i0 + wr + mi * 16 + g;
#pragma unroll
        for (int ni = 0; ni < 8; ++ni) {
            int c0 = j0 + wc + ni * 8 + 2 * t;
            float b0v = 0.f, b1v = 0.f;
            if (bias) {
                if (c0 < Nc)     b0v = bias[c0];
                if (c0 + 1 < Nc) b1v = bias[c0 + 1];
            }
            float v00 = alpha * acc[mi][ni][0] + b0v;
            float v01 = alpha * acc[mi][ni][1] + b1v;
            float v10 = alpha * acc[mi][ni][2] + b0v;
            float v11 = alpha * acc[mi][ni][3] + b1v;
            if (relu) {
                v00 = fmaxf(v00, 0.f); v01 = fmaxf(v01, 0.f);
                v10 = fmaxf(v10, 0.f); v11 = fmaxf(v11, 0.f);
            }
            if (r0 < M) {
                if (c0 < Nc)     Cb[(size_t)r0 * ldc + c0]     = v00;
                if (c0 + 1 < Nc) Cb[(size_t)r0 * ldc + c0 + 1] = v01;
            }
            if (r0 + 8 < M) {
                if (c0 < Nc)     Cb[(size_t)(r0 + 8) * ldc + c0]     = v10;
                if (c0 + 1 < Nc) Cb[(size_t)(r0 + 8) * ldc + c0 + 1] = v11;
            }
        }
    }
}

// ---------------- elementwise kernels ----------------

// Tiled transpose: s[(b,n)][c] = h[b][c][n] + embed[n][c]*mlt[b][n]
__global__ void trans_h(const float* __restrict__ h, const float* __restrict__ embed,
                        const float* __restrict__ mlt) {
    int b = blockIdx.z;
    int n0 = blockIdx.x * 32, c0 = blockIdx.y * 32;
    __shared__ float tile[32][33];
    int tx = threadIdx.x, ty = threadIdx.y;  // (32,8)
#pragma unroll
    for (int l = 0; l < 4; ++l) {
        int c = c0 + ty + l * 8;
        int n = n0 + tx;
        tile[ty + l * 8][tx] = (n < N_) ? h[((size_t)b * D_ + c) * N_ + n] : 0.f;
    }
    __syncthreads();
#pragma unroll
    for (int l = 0; l < 4; ++l) {
        int n = n0 + ty + l * 8;
        if (n < N_) {
            int c = c0 + tx;
            float m = mlt[(size_t)b * N_ + n];
            g_s[((size_t)b * N_ + n) * D_ + c] =
                tile[tx][ty + l * 8] + embed[(size_t)n * D_ + c] * m;
        }
    }
}

// Z0 x-part: g_z[(n*B+b)*320 + c] = x[b][c][n], c < 64
__global__ void trans_x(const float* __restrict__ x) {
    int b = blockIdx.z;
    int n0 = blockIdx.x * 32, c0 = blockIdx.y * 32;
    __shared__ float tile[32][33];
    int tx = threadIdx.x, ty = threadIdx.y;
#pragma unroll
    for (int l = 0; l < 4; ++l) {
        int c = c0 + ty + l * 8;
        int n = n0 + tx;
        tile[ty + l * 8][tx] = (n < N_) ? x[((size_t)b * DIN_ + c) * N_ + n] : 0.f;
    }
    __syncthreads();
#pragma unroll
    for (int l = 0; l < 4; ++l) {
        int n = n0 + ty + l * 8;
        if (n < N_)
            g_z[((size_t)n * B_ + b) * CXG_ + c0 + tx] = tile[tx][ty + l * 8];
    }
}

__global__ void pad_adj(const float* __restrict__ adj) {
    int r = blockIdx.x, c = threadIdx.x;
    g_adjp[(size_t)r * SCLD + c] = (c < N_) ? adj[(size_t)r * N_ + c] : 0.f;
}

__global__ void concat_w(const float* __restrict__ Wu, const float* __restrict__ Wc) {
    int row = blockIdx.x, c = threadIdx.x;
#pragma unroll
    for (int l = 0; l < 5; ++l) {
        int k = c + l * 256;
        g_wuc[(size_t)row * KC_ + k] =
            (row < 256) ? Wu[(size_t)row * KC_ + k] : Wc[(size_t)(row - 256) * KC_ + k];
    }
}
__global__ void concat_b(const float* __restrict__ bu, const float* __restrict__ bc) {
    int o = threadIdx.x;
    g_buc[o] = (o < 256) ? bu[o] : bc[o - 256];
}

__global__ void softmax_rows(float* __restrict__ sc) {
    int row = blockIdx.x * 8 + threadIdx.y;
    float* p = sc + (size_t)row * SCLD;
    int lane = threadIdx.x;
    float mx = -1e30f;
    for (int j = lane; j < N_; j += 32) mx = fmaxf(mx, p[j]);
#pragma unroll
    for (int o = 16; o > 0; o >>= 1) mx = fmaxf(mx, __shfl_xor_sync(0xffffffffu, mx, o));
    float sum = 0.f;
    for (int j = lane; j < N_; j += 32) { float e = expf(p[j] - mx); p[j] = e; sum += e; }
#pragma unroll
    for (int o = 16; o > 0; o >>= 1) sum += __shfl_xor_sync(0xffffffffu, sum, o);
    float inv = 1.f / sum;
    for (int j = lane; j < N_; j += 32) p[j] *= inv;
}

__global__ void add_ln(const float* __restrict__ a, const float* __restrict__ bsrc,
                       const float* __restrict__ w, const float* __restrict__ bb,
                       float* __restrict__ outp) {
    int r = blockIdx.x, c = threadIdx.x;
    size_t idx = (size_t)r * D_ + c;
    float v = a[idx] + bsrc[idx];
    __shared__ float red[256];
    red[c] = v; __syncthreads();
#pragma unroll
    for (int s = 128; s > 0; s >>= 1) { if (c < s) red[c] += red[c + s]; __syncthreads(); }
    float mu = red[0] * (1.f / 256.f);
    __syncthreads();
    float dv = v - mu;
    red[c] = dv * dv; __syncthreads();
#pragma unroll
    for (int s = 128; s > 0; s >>= 1) { if (c < s) red[c] += red[c + s]; __syncthreads(); }
    float var = red[0] * (1.f / 256.f);
    outp[idx] = dv * rsqrtf(var + 1e-5f) * w[c] + bb[c];
}

// LN2(s2 + f1) -> tanh -> h update (h recovered as s - embed*mlt) -> g_hn, Z0 h-part
__global__ void ln2_make_h(const float* __restrict__ a, const float* __restrict__ bsrc,
                           const float* __restrict__ w, const float* __restrict__ bb,
                           const float* __restrict__ embed, const float* __restrict__ mlt,
                           const float* __restrict__ dt, const int* __restrict__ step) {
    int r = blockIdx.x, c = threadIdx.x;
    int b = r / N_, n = r % N_;
    size_t idx = (size_t)r * D_ + c;
    float v = a[idx] + bsrc[idx];
    __shared__ float red[256];
    red[c] = v; __syncthreads();
#pragma unroll
    for (int s = 128; s > 0; s >>= 1) { if (c < s) red[c] += red[c + s]; __syncthreads(); }
    float mu = red[0] * (1.f / 256.f);
    __syncthreads();
    float dv = v - mu;
    red[c] = dv * dv; __syncthreads();
#pragma unroll
    for (int s = 128; s > 0; s >>= 1) { if (c < s) red[c] += red[c + s]; __syncthreads(); }
    float var = red[0] * (1.f / 256.f);
    float s3v = dv * rsqrtf(var + 1e-5f) * w[c] + bb[c];

    float hv = g_s[idx] - embed[(size_t)n * D_ + c] * mlt[(size_t)b * N_ + n];
    float hn;
    if (*step != 0) {
        float d = dt[b];
        hn = sqrtf(1.f - d) * hv - sqrtf(d) * tanhf(s3v);
    } else {
        hn = hv;
    }
    g_hn[idx] = hn;
    g_z[((size_t)n * B_ + b) * CXG_ + DIN_ + c] = hn;
}

__global__ void final_combine(float* __restrict__ outp) {
    int b = blockIdx.z;
    int o0 = blockIdx.y * 32, n0 = blockIdx.x * 32;
    __shared__ float tbuf[32][33];
    int tx = threadIdx.x, ty = threadIdx.y;
#pragma unroll
    for (int s4 = 0; s4 < 4; ++s4) {
        int nl = ty + s4 * 8;
        int n = n0 + nl;
        float val = 0.f;
        if (n < N_) {
            size_t rp = (size_t)n * B_ + b;
            float gu = g_guc[rp * 512 + o0 + tx];
            float gc = g_guc[rp * 512 + 256 + o0 + tx];
            float uu = 1.f / (1.f + expf(-gu));
            float cc = tanhf(gc);
            val = uu * g_hn[((size_t)b * N_ + n) * D_ + o0 + tx] + (1.f - uu) * cc;
        }
        tbuf[nl][tx] = val;
    }
    __syncthreads();
#pragma unroll
    for (int s4 = 0; s4 < 4; ++s4) {
        int ol = ty + s4 * 8;
        int n = n0 + tx;
        if (n < N_)
            outp[((size_t)(b * D_ + o0 + ol)) * N_ + n] = tbuf[tx][ol];
    }
}

// ---------------- launcher ----------------
extern "C" void kernel_launch(void* const* d_in, const int* in_sizes, int n_in,
                              void* d_out, int out_size) {
    const float* x          = (const float*)d_in[0];
    const float* delta_t    = (const float*)d_in[1];
    const float* h          = (const float*)d_in[2];
    const float* adj        = (const float*)d_in[3];
    const float* mlt        = (const float*)d_in[5];
    const int*   step       = (const int*)d_in[7];
    const float* embed      = (const float*)d_in[8];
    const float* in_proj_w  = (const float*)d_in[9];
    const float* in_proj_b  = (const float*)d_in[10];
    const float* out_proj_w = (const float*)d_in[11];
    const float* out_proj_b = (const float*)d_in[12];
    const float* ln1_w      = (const float*)d_in[13];
    const float* ln1_b      = (const float*)d_in[14];
    const float* ln2_w      = (const float*)d_in[15];
    const float* ln2_b      = (const float*)d_in[16];
    const float* ffn_w1     = (const float*)d_in[17];
    const float* ffn_b1     = (const float*)d_in[18];
    const float* ffn_w2     = (const float*)d_in[19];
    const float* ffn_b2     = (const float*)d_in[20];
    const float* W_u        = (const float*)d_in[21];
    const float* b_u        = (const float*)d_in[22];
    const float* W_c        = (const float*)d_in[23];
    const float* b_c        = (const float*)d_in[24];
    float* outp = (float*)d_out;

    void *vp;
    cudaGetSymbolAddress(&vp, g_s);    float* ps   = (float*)vp;
    cudaGetSymbolAddress(&vp, g_qkv);  float* pq   = (float*)vp;
    cudaGetSymbolAddress(&vp, g_sc);   float* psc  = (float*)vp;
    cudaGetSymbolAddress(&vp, g_adjp); float* padj = (float*)vp;
    cudaGetSymbolAddress(&vp, g_o);    float* po   = (float*)vp;
    cudaGetSymbolAddress(&vp, g_s2);   float* ps2  = (float*)vp;
    cudaGetSymbolAddress(&vp, g_f1);   float* pf1  = (float*)vp;
    cudaGetSymbolAddress(&vp, g_z);    float* pz   = (float*)vp;
    cudaGetSymbolAddress(&vp, g_guc);  float* pguc = (float*)vp;
    cudaGetSymbolAddress(&vp, g_wuc);  float* pwuc = (float*)vp;
    cudaGetSymbolAddress(&vp, g_buc);  float* pbuc = (float*)vp;

    static const int SM256 = 3 * (128 * 36 + 256 * 36) * 4;   // 165888
    cudaFuncSetAttribute(mma_gemm<256, 3>, cudaFuncAttributeMaxDynamicSharedMemorySize, SM256);

    // 0. prep
    pad_adj<<<N_, SCLD>>>(adj);
    concat_w<<<512, 256>>>(W_u, W_c);
    concat_b<<<1, 512>>>(b_u, b_c);

    // 1. transformer input (tiled transpose)
    trans_h<<<dim3(7, 8, B_), dim3(32, 8)>>>(h, embed, mlt);
    // Z0 x-part
    trans_x<<<dim3(7, 2, B_), dim3(32, 8)>>>(x);

    // 2. QKV
    mma_gemm<256, 3><<<dim3(3, 414, 1), 256, SM256>>>(ps, in_proj_w, in_proj_b, pq,
        NB_, QKVLD, 256, 256, 256, QKVLD, 0, 0, 0, 1.f, 1, 0, 0, 0);

    // 3. scores: per-batch Q @ K^T / 16
    mma_gemm<256, 3><<<dim3(1, 2, B_), 256, SM256>>>(pq, pq + 256, nullptr, psc,
        N_, N_, 256, QKVLD, QKVLD, SCLD,
        (long long)N_ * QKVLD, (long long)N_ * QKVLD, (long long)N_ * SCLD,
        1.f / 16.f, 1, 0, 0, 0);

    // 4. softmax
    softmax_rows<<<NB_ / 8, dim3(32, 8)>>>(psc);

    // 5. attn @ V (NN)
    mma_gemm<256, 3><<<dim3(1, 2, B_), 256, SM256>>>(psc, pq + 512, nullptr, po,
        N_, 256, N_, SCLD, QKVLD, 256,
        (long long)N_ * SCLD, (long long)N_ * QKVLD, (long long)N_ * 256,
        1.f, 0, 0, 0, 0);

    // 6. out projection
    mma_gemm<256, 3><<<dim3(1, 414, 1), 256, SM256>>>(po, out_proj_w, out_proj_b, pf1,
        NB_, 256, 256, 256, 256, 256, 0, 0, 0, 1.f, 1, 0, 0, 0);

    // 7. LN1
    add_ln<<<NB_, 256>>>(ps, pf1, ln1_w, ln1_b, ps2);

    // 8. FFN
    mma_gemm<256, 3><<<dim3(1, 414, 1), 256, SM256>>>(ps2, ffn_w1, ffn_b1, po,
        NB_, 256, 256, 256, 256, 256, 0, 0, 0, 1.f, 1, 1, 0, 0);
    mma_gemm<256, 3><<<dim3(1, 414, 1), 256, SM256>>>(po, ffn_w2, ffn_b2, pf1,
        NB_, 256, 256, 256, 256, 256, 0, 0, 0, 1.f, 1, 0, 0, 0);

    // 9+10. LN2 + h update + Z0 h-part (fused)
    ln2_make_h<<<NB_, 256>>>(ps2, pf1, ln2_w, ln2_b, embed, mlt, delta_t, step);

    // 11. diffusion: Z_k = adj @ Z_{k-1}, ONE dense GEMM per order
    //     (M=207, Ncols=81920, K=207)
    for (int k = 1; k <= 3; ++k) {
        mma_gemm<256, 3><<<dim3(ZROW / 256, 2, 1), 256, SM256>>>(padj,
            pz + (size_t)(k - 1) * ZK, nullptr, pz + (size_t)k * ZK,
            N_, ZROW, N_, SCLD, ZROW, ZROW,
            0, 0, 0, 1.f, 0, 0, 0, 0);
    }

    // 12. fused gates over blocked-K z: rows r' = n*B+b, lda=320,
    //     k-block stride = ZK (extra = ZK - 320)
    mma_gemm<256, 3><<<dim3(2, 414, 1), 256, SM256>>>(pz, pwuc, pbuc, pguc,
        NB_, 512, KC_, CXG_, KC_, 512, 0, 0, 0, 1.f, 1, 0,
        CXG_, (long long)ZK - CXG_);

    // 13. gated combine + transpose
    final_combine<<<dim3(7, 8, B_), dim3(32, 8)>>>(outp);
}

// round 8
// speedup vs baseline: 4.5375x; 1.4060x over previous
#include <cuda_runtime.h>
#include <cuda_fp16.h>
#include <math.h>
#include <stdint.h>

// Problem constants
#define B_    256
#define N_    207
#define D_    256
#define DIN_  64
#define CXG_  320
#define KC_   1280
#define NB_   52992
#define QKVLD 768
#define SCLD  208
#define ZROW  81920
#define ZK    ((size_t)NB_ * CXG_)

// ---------------- scratch ----------------
__device__ float  g_s   [(size_t)NB_ * D_];      // fp32 s (residual / h recovery)
__device__ __half g_sh  [(size_t)NB_ * D_];      // fp16 s (QKV A)
__device__ __half g_qkvh[(size_t)NB_ * QKVLD];   // fp16 qkv
__device__ float  g_sc  [(size_t)B_ * N_ * SCLD + 256];  // fp32 scores
__device__ __half g_sch [(size_t)B_ * N_ * SCLD + 256];  // fp16 softmaxed
__device__ __half g_adjh[(size_t)N_ * SCLD];
__device__ __half g_oh  [(size_t)NB_ * D_];      // attn out (fp16)
__device__ float  g_f1  [(size_t)NB_ * D_];      // fp32 temp (proj / ffn2)
__device__ float  g_s2  [(size_t)NB_ * D_];      // post-LN1 fp32
__device__ __half g_s2h [(size_t)NB_ * D_];      // post-LN1 fp16 (FFN1 A)
__device__ __half g_poh [(size_t)NB_ * D_];      // ffn hidden fp16
__device__ float  g_hn  [(size_t)NB_ * D_];
__device__ __half g_zh  [4 * ZK];                // diffusion features fp16 [k][n][b][c]
__device__ float  g_guc [(size_t)NB_ * 512];
__device__ __half g_wuch[(size_t)512 * KC_];
__device__ float  g_buc [512];
__device__ __half g_wqh [(size_t)QKVLD * D_];
__device__ __half g_woh [(size_t)D_ * D_];
__device__ __half g_w1h [(size_t)D_ * D_];
__device__ __half g_w2h [(size_t)D_ * D_];

// ---------------- helpers ----------------
__device__ __forceinline__ void cpa16(void* dst, const void* src, int srcbytes) {
    unsigned d = (unsigned)__cvta_generic_to_shared(dst);
    asm volatile("cp.async.cg.shared.global [%0], [%1], 16, %2;\n"
                 :: "r"(d), "l"(src), "r"(srcbytes));
}
__device__ __forceinline__ void cp_commit() {
    asm volatile("cp.async.commit_group;\n" ::: "memory");
}
template <int NGRP>
__device__ __forceinline__ void cp_wait() {
    asm volatile("cp.async.wait_group %0;\n" :: "n"(NGRP) : "memory");
}

__device__ __forceinline__ void mma_f16(float* c, const unsigned* a, const unsigned* b) {
    asm volatile(
        "mma.sync.aligned.m16n8k16.row.col.f32.f16.f16.f32 "
        "{%0,%1,%2,%3}, {%4,%5,%6,%7}, {%8,%9}, {%0,%1,%2,%3};\n"
        : "+f"(c[0]), "+f"(c[1]), "+f"(c[2]), "+f"(c[3])
        : "r"(a[0]), "r"(a[1]), "r"(a[2]), "r"(a[3]), "r"(b[0]), "r"(b[1]));
}

// ---------------- FP16 tensor-core GEMM ----------------
// C = alpha * A @ op(B) + bias, optional relu; out fp32 or fp16.
// transB: B is Nc x K row-major; else B is K x Nc row-major. Batched via z.
// BM=128, BN=256, BK=64 (halfs), 8 warps, warp tile 64x64, m16n8k16.
// A smem [m][k] stride 72 halfs; B transB [n][k] stride 72; B NN [k][n] stride 264.
// A may be blocked-K (aksub halfs per block, akstr extra halfs per block).
#define AS_H   (128 * 72)
#define BS_H   (256 * 72)      // >= 64*264
#define STG_H  (AS_H + BS_H)

__device__ __forceinline__ void load_chunk_h(
    __half* As, __half* Bs, const __half* Ab, const __half* Bb,
    int i0, int j0, int M, int Nc, int K, int lda, int ldb,
    int k0, int tid, int transB)
{
#pragma unroll
    for (int l = 0; l < 4; ++l) {
        int e = tid + l * 256;
        int row = e >> 3, q = e & 7;
        int gr = i0 + row; if (gr > M - 1) gr = M - 1;
        int gk = k0 + q * 8;
        int rem = K - gk;
        int bytes = rem >= 8 ? 16 : (rem > 0 ? rem * 2 : 0);
        cpa16(As + row * 72 + q * 8, Ab + (size_t)gr * lda + (bytes ? gk : 0), bytes);
    }
    if (transB) {
#pragma unroll
        for (int l = 0; l < 8; ++l) {
            int e = tid + l * 256;
            int row = e >> 3, q = e & 7;
            int gr = j0 + row; if (gr > Nc - 1) gr = Nc - 1;
            int gk = k0 + q * 8;
            int rem = K - gk;
            int bytes = rem >= 8 ? 16 : (rem > 0 ? rem * 2 : 0);
            cpa16(Bs + row * 72 + q * 8, Bb + (size_t)gr * ldb + (bytes ? gk : 0), bytes);
        }
    } else {
#pragma unroll
        for (int l = 0; l < 8; ++l) {
            int e = tid + l * 256;
            int kk = e >> 5;
            int nq = (e & 31) * 8;
            int gk = k0 + kk;
            int bytes = (gk < K) ? 16 : 0;
            cpa16(Bs + kk * 264 + nq, Bb + (size_t)(bytes ? gk : 0) * ldb + j0 + nq, bytes);
        }
    }
}

__global__ __launch_bounds__(256, 1) void hgemm(
    const __half* __restrict__ A, const __half* __restrict__ Bm,
    const float* __restrict__ bias, void* __restrict__ Cp,
    int M, int Nc, int K, int lda, int ldb, int ldc,
    long long sA, long long sB, long long sC,
    float alpha, int transB, int relu, int outHalf,
    int aksub, long long akstr)
{
    extern __shared__ __half smh[];

    const __half* Ab = A  + (size_t)blockIdx.z * sA;
    const __half* Bb = Bm + (size_t)blockIdx.z * sB;

    const int tid  = threadIdx.x;
    const int lane = tid & 31;
    const int wid  = tid >> 5;
    const int wr   = (wid & 1) * 64;
    const int wc   = (wid >> 1) * 64;
    const int g    = lane >> 2;
    const int t    = lane & 3;

    const int i0 = blockIdx.y * 128;
    const int j0 = blockIdx.x * 256;

    float acc[4][8][4];
#pragma unroll
    for (int mi = 0; mi < 4; ++mi)
#pragma unroll
        for (int ni = 0; ni < 8; ++ni)
#pragma unroll
            for (int q = 0; q < 4; ++q) acc[mi][ni][q] = 0.f;

    const int nk = (K + 63) / 64;

#pragma unroll
    for (int s = 0; s < 2; ++s) {
        if (s < nk) {
            const __half* AbC = Ab + (aksub ? (long long)((s * 64) / aksub) * akstr : 0);
            load_chunk_h(smh + s * STG_H, smh + s * STG_H + AS_H, AbC, Bb,
                         i0, j0, M, Nc, K, lda, ldb, s * 64, tid, transB);
        }
        cp_commit();
    }

    for (int c = 0; c < nk; ++c) {
        int pf = c + 2;
        if (pf < nk) {
            int st = pf % 3;
            const __half* AbC = Ab + (aksub ? (long long)((pf * 64) / aksub) * akstr : 0);
            load_chunk_h(smh + st * STG_H, smh + st * STG_H + AS_H, AbC, Bb,
                         i0, j0, M, Nc, K, lda, ldb, pf * 64, tid, transB);
        }
        cp_commit();
        cp_wait<2>();
        __syncthreads();

        const __half* AsH = smh + (c % 3) * STG_H;
        const __half* BsH = AsH + AS_H;

#pragma unroll
        for (int k16 = 0; k16 < 4; ++k16) {
            const int kb = k16 * 16;
            unsigned af[4][4];
#pragma unroll
            for (int mi = 0; mi < 4; ++mi) {
                int r = wr + mi * 16 + g;
                af[mi][0] = *(const unsigned*)&AsH[(size_t)r * 72 + kb + 2 * t];
                af[mi][1] = *(const unsigned*)&AsH[(size_t)(r + 8) * 72 + kb + 2 * t];
                af[mi][2] = *(const unsigned*)&AsH[(size_t)r * 72 + kb + 8 + 2 * t];
                af[mi][3] = *(const unsigned*)&AsH[(size_t)(r + 8) * 72 + kb + 8 + 2 * t];
            }
            unsigned bf[8][2];
            if (transB) {
#pragma unroll
                for (int ni = 0; ni < 8; ++ni) {
                    int cc = wc + ni * 8 + g;
                    bf[ni][0] = *(const unsigned*)&BsH[(size_t)cc * 72 + kb + 2 * t];
                    bf[ni][1] = *(const unsigned*)&BsH[(size_t)cc * 72 + kb + 8 + 2 * t];
                }
            } else {
                const unsigned short* Bnn = (const unsigned short*)BsH;
#pragma unroll
                for (int ni = 0; ni < 8; ++ni) {
                    int cc = wc + ni * 8 + g;
                    unsigned lo0 = Bnn[(size_t)(kb + 2 * t) * 264 + cc];
                    unsigned hi0 = Bnn[(size_t)(kb + 2 * t + 1) * 264 + cc];
                    unsigned lo1 = Bnn[(size_t)(kb + 8 + 2 * t) * 264 + cc];
                    unsigned hi1 = Bnn[(size_t)(kb + 9 + 2 * t) * 264 + cc];
                    bf[ni][0] = lo0 | (hi0 << 16);
                    bf[ni][1] = lo1 | (hi1 << 16);
                }
            }
#pragma unroll
            for (int mi = 0; mi < 4; ++mi)
#pragma unroll
                for (int ni = 0; ni < 8; ++ni)
                    mma_f16(acc[mi][ni], af[mi], bf[ni]);
        }
        __syncthreads();
    }
    cp_wait<0>();

    // epilogue
    float* Cf = (float*)Cp + (size_t)blockIdx.z * sC;
    __half* Ch = (__half*)Cp + (size_t)blockIdx.z * sC;
#pragma unroll
    for (int mi = 0; mi < 4; ++mi) {
        int r0 = i0 + wr + mi * 16 + g;
#pragma unroll
        for (int ni = 0; ni < 8; ++ni) {
            int c0 = j0 + wc + ni * 8 + 2 * t;
            float b0v = 0.f, b1v = 0.f;
            if (bias && c0 < Nc) { b0v = bias[c0]; b1v = (c0 + 1 < Nc) ? bias[c0 + 1] : 0.f; }
            float v00 = alpha * acc[mi][ni][0] + b0v;
            float v01 = alpha * acc[mi][ni][1] + b1v;
            float v10 = alpha * acc[mi][ni][2] + b0v;
            float v11 = alpha * acc[mi][ni][3] + b1v;
            if (relu) {
                v00 = fmaxf(v00, 0.f); v01 = fmaxf(v01, 0.f);
                v10 = fmaxf(v10, 0.f); v11 = fmaxf(v11, 0.f);
            }
            if (outHalf) {
                if (r0 < M && c0 < Nc)
                    *(__half2*)&Ch[(size_t)r0 * ldc + c0] = __floats2half2_rn(v00, v01);
                if (r0 + 8 < M && c0 < Nc)
                    *(__half2*)&Ch[(size_t)(r0 + 8) * ldc + c0] = __floats2half2_rn(v10, v11);
            } else {
                if (r0 < M) {
                    if (c0 < Nc)     Cf[(size_t)r0 * ldc + c0]     = v00;
                    if (c0 + 1 < Nc) Cf[(size_t)r0 * ldc + c0 + 1] = v01;
                }
                if (r0 + 8 < M) {
                    if (c0 < Nc)     Cf[(size_t)(r0 + 8) * ldc + c0]     = v10;
                    if (c0 + 1 < Nc) Cf[(size_t)(r0 + 8) * ldc + c0 + 1] = v11;
                }
            }
        }
    }
}

// ---------------- elementwise kernels ----------------

__global__ void cvt_h(const float* __restrict__ src, __half* __restrict__ dst, int n) {
    int i = blockIdx.x * 256 + threadIdx.x;
    if (i < n) dst[i] = __float2half(src[i]);
}

__global__ void trans_h(const float* __restrict__ h, const float* __restrict__ embed,
                        const float* __restrict__ mlt) {
    int b = blockIdx.z;
    int n0 = blockIdx.x * 32, c0 = blockIdx.y * 32;
    __shared__ float tile[32][33];
    int tx = threadIdx.x, ty = threadIdx.y;
#pragma unroll
    for (int l = 0; l < 4; ++l) {
        int c = c0 + ty + l * 8;
        int n = n0 + tx;
        tile[ty + l * 8][tx] = (n < N_) ? h[((size_t)b * D_ + c) * N_ + n] : 0.f;
    }
    __syncthreads();
#pragma unroll
    for (int l = 0; l < 4; ++l) {
        int n = n0 + ty + l * 8;
        if (n < N_) {
            int c = c0 + tx;
            float m = mlt[(size_t)b * N_ + n];
            float v = tile[tx][ty + l * 8] + embed[(size_t)n * D_ + c] * m;
            size_t idx = ((size_t)b * N_ + n) * D_ + c;
            g_s[idx] = v;
            g_sh[idx] = __float2half(v);
        }
    }
}

__global__ void trans_x(const float* __restrict__ x) {
    int b = blockIdx.z;
    int n0 = blockIdx.x * 32, c0 = blockIdx.y * 32;
    __shared__ float tile[32][33];
    int tx = threadIdx.x, ty = threadIdx.y;
#pragma unroll
    for (int l = 0; l < 4; ++l) {
        int c = c0 + ty + l * 8;
        int n = n0 + tx;
        tile[ty + l * 8][tx] = (n < N_) ? x[((size_t)b * DIN_ + c) * N_ + n] : 0.f;
    }
    __syncthreads();
#pragma unroll
    for (int l = 0; l < 4; ++l) {
        int n = n0 + ty + l * 8;
        if (n < N_)
            g_zh[((size_t)n * B_ + b) * CXG_ + c0 + tx] = __float2half(tile[tx][ty + l * 8]);
    }
}

__global__ void pad_adj(const float* __restrict__ adj) {
    int r = blockIdx.x, c = threadIdx.x;
    g_adjh[(size_t)r * SCLD + c] = __float2half((c < N_) ? adj[(size_t)r * N_ + c] : 0.f);
}

__global__ void concat_w(const float* __restrict__ Wu, const float* __restrict__ Wc) {
    int row = blockIdx.x, c = threadIdx.x;
#pragma unroll
    for (int l = 0; l < 5; ++l) {
        int k = c + l * 256;
        float v = (row < 256) ? Wu[(size_t)row * KC_ + k] : Wc[(size_t)(row - 256) * KC_ + k];
        g_wuch[(size_t)row * KC_ + k] = __float2half(v);
    }
}
__global__ void concat_b(const float* __restrict__ bu, const float* __restrict__ bc) {
    int o = threadIdx.x;
    g_buc[o] = (o < 256) ? bu[o] : bc[o - 256];
}

__global__ void softmax_rows(const float* __restrict__ sc, __half* __restrict__ sch) {
    int row = blockIdx.x * 8 + threadIdx.y;
    const float* p = sc + (size_t)row * SCLD;
    __half* ph = sch + (size_t)row * SCLD;
    int lane = threadIdx.x;
    float mx = -1e30f;
    for (int j = lane; j < N_; j += 32) mx = fmaxf(mx, p[j]);
#pragma unroll
    for (int o = 16; o > 0; o >>= 1) mx = fmaxf(mx, __shfl_xor_sync(0xffffffffu, mx, o));
    float sum = 0.f;
    float ev[7];
    int cnt = 0;
    for (int j = lane; j < N_; j += 32) { float e = expf(p[j] - mx); ev[cnt++] = e; sum += e; }
#pragma unroll
    for (int o = 16; o > 0; o >>= 1) sum += __shfl_xor_sync(0xffffffffu, sum, o);
    float inv = 1.f / sum;
    cnt = 0;
    for (int j = lane; j < N_; j += 32) ph[j] = __float2half(ev[cnt++] * inv);
}

__global__ void add_ln(const float* __restrict__ a, const float* __restrict__ bsrc,
                       const float* __restrict__ w, const float* __restrict__ bb,
                       float* __restrict__ outf, __half* __restrict__ outh) {
    int r = blockIdx.x, c = threadIdx.x;
    size_t idx = (size_t)r * D_ + c;
    float v = a[idx] + bsrc[idx];
    __shared__ float red[256];
    red[c] = v; __syncthreads();
#pragma unroll
    for (int s = 128; s > 0; s >>= 1) { if (c < s) red[c] += red[c + s]; __syncthreads(); }
    float mu = red[0] * (1.f / 256.f);
    __syncthreads();
    float dv = v - mu;
    red[c] = dv * dv; __syncthreads();
#pragma unroll
    for (int s = 128; s > 0; s >>= 1) { if (c < s) red[c] += red[c + s]; __syncthreads(); }
    float var = red[0] * (1.f / 256.f);
    float o = dv * rsqrtf(var + 1e-5f) * w[c] + bb[c];
    outf[idx] = o;
    outh[idx] = __float2half(o);
}

__global__ void ln2_make_h(const float* __restrict__ a, const float* __restrict__ bsrc,
                           const float* __restrict__ w, const float* __restrict__ bb,
                           const float* __restrict__ embed, const float* __restrict__ mlt,
                           const float* __restrict__ dt, const int* __restrict__ step) {
    int r = blockIdx.x, c = threadIdx.x;
    int b = r / N_, n = r % N_;
    size_t idx = (size_t)r * D_ + c;
    float v = a[idx] + bsrc[idx];
    __shared__ float red[256];
    red[c] = v; __syncthreads();
#pragma unroll
    for (int s = 128; s > 0; s >>= 1) { if (c < s) red[c] += red[c + s]; __syncthreads(); }
    float mu = red[0] * (1.f / 256.f);
    __syncthreads();
    float dv = v - mu;
    red[c] = dv * dv; __syncthreads();
#pragma unroll
    for (int s = 128; s > 0; s >>= 1) { if (c < s) red[c] += red[c + s]; __syncthreads(); }
    float var = red[0] * (1.f / 256.f);
    float s3v = dv * rsqrtf(var + 1e-5f) * w[c] + bb[c];

    float hv = g_s[idx] - embed[(size_t)n * D_ + c] * mlt[(size_t)b * N_ + n];
    float hn;
    if (*step != 0) {
        float d = dt[b];
        hn = sqrtf(1.f - d) * hv - sqrtf(d) * tanhf(s3v);
    } else {
        hn = hv;
    }
    g_hn[idx] = hn;
    g_zh[((size_t)n * B_ + b) * CXG_ + DIN_ + c] = __float2half(hn);
}

__global__ void final_combine(float* __restrict__ outp) {
    int b = blockIdx.z;
    int o0 = blockIdx.y * 32, n0 = blockIdx.x * 32;
    __shared__ float tbuf[32][33];
    int tx = threadIdx.x, ty = threadIdx.y;
#pragma unroll
    for (int s4 = 0; s4 < 4; ++s4) {
        int nl = ty + s4 * 8;
        int n = n0 + nl;
        float val = 0.f;
        if (n < N_) {
            size_t rp = (size_t)n * B_ + b;
            float gu = g_guc[rp * 512 + o0 + tx];
            float gc = g_guc[rp * 512 + 256 + o0 + tx];
            float uu = 1.f / (1.f + expf(-gu));
            float cc = tanhf(gc);
            val = uu * g_hn[((size_t)b * N_ + n) * D_ + o0 + tx] + (1.f - uu) * cc;
        }
        tbuf[nl][tx] = val;
    }
    __syncthreads();
#pragma unroll
    for (int s4 = 0; s4 < 4; ++s4) {
        int ol = ty + s4 * 8;
        int n = n0 + tx;
        if (n < N_)
            outp[((size_t)(b * D_ + o0 + ol)) * N_ + n] = tbuf[tx][ol];
    }
}

// ---------------- launcher ----------------
extern "C" void kernel_launch(void* const* d_in, const int* in_sizes, int n_in,
                              void* d_out, int out_size) {
    const float* x          = (const float*)d_in[0];
    const float* delta_t    = (const float*)d_in[1];
    const float* h          = (const float*)d_in[2];
    const float* adj        = (const float*)d_in[3];
    const float* mlt        = (const float*)d_in[5];
    const int*   step       = (const int*)d_in[7];
    const float* embed      = (const float*)d_in[8];
    const float* in_proj_w  = (const float*)d_in[9];
    const float* in_proj_b  = (const float*)d_in[10];
    const float* out_proj_w = (const float*)d_in[11];
    const float* out_proj_b = (const float*)d_in[12];
    const float* ln1_w      = (const float*)d_in[13];
    const float* ln1_b      = (const float*)d_in[14];
    const float* ln2_w      = (const float*)d_in[15];
    const float* ln2_b      = (const float*)d_in[16];
    const float* ffn_w1     = (const float*)d_in[17];
    const float* ffn_b1     = (const float*)d_in[18];
    const float* ffn_w2     = (const float*)d_in[19];
    const float* ffn_b2     = (const float*)d_in[20];
    const float* W_u        = (const float*)d_in[21];
    const float* b_u        = (const float*)d_in[22];
    const float* W_c        = (const float*)d_in[23];
    const float* b_c        = (const float*)d_in[24];
    float* outp = (float*)d_out;

    void *vp;
    cudaGetSymbolAddress(&vp, g_s);    float*  ps   = (float*)vp;
    cudaGetSymbolAddress(&vp, g_sh);   __half* psh  = (__half*)vp;
    cudaGetSymbolAddress(&vp, g_qkvh); __half* pqh  = (__half*)vp;
    cudaGetSymbolAddress(&vp, g_sc);   float*  psc  = (float*)vp;
    cudaGetSymbolAddress(&vp, g_sch);  __half* psch = (__half*)vp;
    cudaGetSymbolAddress(&vp, g_adjh); __half* padh = (__half*)vp;
    cudaGetSymbolAddress(&vp, g_oh);   __half* poh  = (__half*)vp;
    cudaGetSymbolAddress(&vp, g_f1);   float*  pf1  = (float*)vp;
    cudaGetSymbolAddress(&vp, g_s2);   float*  ps2  = (float*)vp;
    cudaGetSymbolAddress(&vp, g_s2h);  __half* ps2h = (__half*)vp;
    cudaGetSymbolAddress(&vp, g_poh);  __half* ppoh = (__half*)vp;
    cudaGetSymbolAddress(&vp, g_zh);   __half* pzh  = (__half*)vp;
    cudaGetSymbolAddress(&vp, g_guc);  float*  pguc = (float*)vp;
    cudaGetSymbolAddress(&vp, g_wuch); __half* pwuh = (__half*)vp;
    cudaGetSymbolAddress(&vp, g_buc);  float*  pbuc = (float*)vp;
    cudaGetSymbolAddress(&vp, g_wqh);  __half* pwq  = (__half*)vp;
    cudaGetSymbolAddress(&vp, g_woh);  __half* pwo  = (__half*)vp;
    cudaGetSymbolAddress(&vp, g_w1h);  __half* pw1  = (__half*)vp;
    cudaGetSymbolAddress(&vp, g_w2h);  __half* pw2  = (__half*)vp;

    static const int SMH = 3 * STG_H * 2;   // 165888 bytes
    cudaFuncSetAttribute(hgemm, cudaFuncAttributeMaxDynamicSharedMemorySize, SMH);

    // 0. prep: fp16 conversions
    pad_adj<<<N_, SCLD>>>(adj);
    concat_w<<<512, 256>>>(W_u, W_c);
    concat_b<<<1, 512>>>(b_u, b_c);
    cvt_h<<<(QKVLD * D_ + 255) / 256, 256>>>(in_proj_w, pwq, QKVLD * D_);
    cvt_h<<<(D_ * D_ + 255) / 256, 256>>>(out_proj_w, pwo, D_ * D_);
    cvt_h<<<(D_ * D_ + 255) / 256, 256>>>(ffn_w1, pw1, D_ * D_);
    cvt_h<<<(D_ * D_ + 255) / 256, 256>>>(ffn_w2, pw2, D_ * D_);

    // 1. transformer input + Z0 x-part
    trans_h<<<dim3(7, 8, B_), dim3(32, 8)>>>(h, embed, mlt);
    trans_x<<<dim3(7, 2, B_), dim3(32, 8)>>>(x);

    // 2. QKV: (NB x 256) @ (768 x 256)^T + bias -> fp16
    hgemm<<<dim3(3, 414, 1), 256, SMH>>>(psh, pwq, in_proj_b, pqh,
        NB_, QKVLD, 256, 256, 256, QKVLD, 0, 0, 0, 1.f, 1, 0, 1, 0, 0);

    // 3. scores: per-batch Q @ K^T / 16 -> fp32
    hgemm<<<dim3(1, 2, B_), 256, SMH>>>(pqh, pqh + 256, nullptr, psc,
        N_, N_, 256, QKVLD, QKVLD, SCLD,
        (long long)N_ * QKVLD, (long long)N_ * QKVLD, (long long)N_ * SCLD,
        1.f / 16.f, 1, 0, 0, 0, 0);

    // 4. softmax -> fp16
    softmax_rows<<<NB_ / 8, dim3(32, 8)>>>(psc, psch);

    // 5. attn @ V (NN) -> fp16
    hgemm<<<dim3(1, 2, B_), 256, SMH>>>(psch, pqh + 512, nullptr, poh,
        N_, 256, N_, SCLD, QKVLD, 256,
        (long long)N_ * SCLD, (long long)N_ * QKVLD, (long long)N_ * 256,
        1.f, 0, 0, 1, 0, 0);

    // 6. out projection -> fp32
    hgemm<<<dim3(1, 414, 1), 256, SMH>>>(poh, pwo, out_proj_b, pf1,
        NB_, 256, 256, 256, 256, 256, 0, 0, 0, 1.f, 1, 0, 0, 0, 0);

    // 7. LN1 -> fp32 + fp16
    add_ln<<<NB_, 256>>>(ps, pf1, ln1_w, ln1_b, ps2, ps2h);

    // 8. FFN
    hgemm<<<dim3(1, 414, 1), 256, SMH>>>(ps2h, pw1, ffn_b1, ppoh,
        NB_, 256, 256, 256, 256, 256, 0, 0, 0, 1.f, 1, 1, 1, 0, 0);
    hgemm<<<dim3(1, 414, 1), 256, SMH>>>(ppoh, pw2, ffn_b2, pf1,
        NB_, 256, 256, 256, 256, 256, 0, 0, 0, 1.f, 1, 0, 0, 0, 0);

    // 9+10. LN2 + h update + Z0 h-part (fused)
    ln2_make_h<<<NB_, 256>>>(ps2, pf1, ln2_w, ln2_b, embed, mlt, delta_t, step);

    // 11. diffusion: Z_k = adj @ Z_{k-1}, dense NN (207 x 81920 x 207) -> fp16
    for (int k = 1; k <= 3; ++k) {
        hgemm<<<dim3(ZROW / 256, 2, 1), 256, SMH>>>(padh,
            pzh + (size_t)(k - 1) * ZK, nullptr, pzh + (size_t)k * ZK,
            N_, ZROW, N_, SCLD, ZROW, ZROW,
            0, 0, 0, 1.f, 0, 0, 1, 0, 0);
    }

    // 12. fused gates (blocked-K z): (NB x 1280) @ (512 x 1280)^T + bias -> fp32
    hgemm<<<dim3(2, 414, 1), 256, SMH>>>(pzh, pwuh, pbuc, pguc,
        NB_, 512, KC_, CXG_, KC_, 512, 0, 0, 0, 1.f, 1, 0, 0,
        CXG_, (long long)ZK - CXG_);

    // 13. gated combine + transpose
    final_combine<<<dim3(7, 8, B_), dim3(32, 8)>>>(outp);
}

// round 9
// speedup vs baseline: 4.8568x; 1.0704x over previous
#include <cuda_runtime.h>
#include <cuda_fp16.h>
#include <math.h>
#include <stdint.h>

// Problem constants
#define B_    256
#define N_    207
#define D_    256
#define DIN_  64
#define CXG_  320
#define KC_   1280
#define NB_   52992
#define QKVLD 768
#define SCLD  208
#define ZROW  81920
#define ZK    ((size_t)NB_ * CXG_)

// ---------------- scratch ----------------
__device__ float  g_s   [(size_t)NB_ * D_];
__device__ __half g_sh  [(size_t)NB_ * D_];
__device__ __half g_qkvh[(size_t)NB_ * QKVLD];
__device__ float  g_sc  [(size_t)B_ * N_ * SCLD + 256];
__device__ __half g_sch [(size_t)B_ * N_ * SCLD + 256];
__device__ __half g_adjh[(size_t)N_ * SCLD];
__device__ __half g_oh  [(size_t)NB_ * D_];
__device__ float  g_f1  [(size_t)NB_ * D_];
__device__ float  g_s2  [(size_t)NB_ * D_];
__device__ __half g_s2h [(size_t)NB_ * D_];
__device__ __half g_poh [(size_t)NB_ * D_];
__device__ float  g_hn  [(size_t)NB_ * D_];
__device__ __half g_zh  [4 * ZK];
__device__ float  g_guc [(size_t)NB_ * 512];
__device__ __half g_wuch[(size_t)512 * KC_];
__device__ float  g_buc [512];
__device__ __half g_wqh [(size_t)QKVLD * D_];
__device__ __half g_woh [(size_t)D_ * D_];
__device__ __half g_w1h [(size_t)D_ * D_];
__device__ __half g_w2h [(size_t)D_ * D_];

// ---------------- helpers ----------------
__device__ __forceinline__ void cpa16(void* dst, const void* src, int srcbytes) {
    unsigned d = (unsigned)__cvta_generic_to_shared(dst);
    asm volatile("cp.async.cg.shared.global [%0], [%1], 16, %2;\n"
                 :: "r"(d), "l"(src), "r"(srcbytes));
}
__device__ __forceinline__ void cp_commit() {
    asm volatile("cp.async.commit_group;\n" ::: "memory");
}
template <int NGRP>
__device__ __forceinline__ void cp_wait() {
    asm volatile("cp.async.wait_group %0;\n" :: "n"(NGRP) : "memory");
}

__device__ __forceinline__ void mma_f16(float* c, const unsigned* a, const unsigned* b) {
    asm volatile(
        "mma.sync.aligned.m16n8k16.row.col.f32.f16.f16.f32 "
        "{%0,%1,%2,%3}, {%4,%5,%6,%7}, {%8,%9}, {%0,%1,%2,%3};\n"
        : "+f"(c[0]), "+f"(c[1]), "+f"(c[2]), "+f"(c[3])
        : "r"(a[0]), "r"(a[1]), "r"(a[2]), "r"(a[3]), "r"(b[0]), "r"(b[1]));
}

#define LDSM_X4(r0, r1, r2, r3, a) \
    asm volatile("ldmatrix.sync.aligned.m8n8.x4.shared.b16 {%0,%1,%2,%3}, [%4];" \
                 : "=r"(r0), "=r"(r1), "=r"(r2), "=r"(r3) : "r"(a))
#define LDSM_X4_T(r0, r1, r2, r3, a) \
    asm volatile("ldmatrix.sync.aligned.m8n8.x4.trans.shared.b16 {%0,%1,%2,%3}, [%4];" \
                 : "=r"(r0), "=r"(r1), "=r"(r2), "=r"(r3) : "r"(a))

// ---------------- FP16 tensor-core GEMM ----------------
// C = alpha * A @ op(B) + bias, optional relu; out fp32 or fp16.
// BM=128, BN=256, BK=64 halfs, 8 warps, warp tile 64x64, m16n8k16, LDSM fragments.
#define AS_H   (128 * 72)
#define BS_H   (256 * 72)      // >= 64*264
#define STG_H  (AS_H + BS_H)

__device__ __forceinline__ void load_chunk_h(
    __half* As, __half* Bs, const __half* Ab, const __half* Bb,
    int i0, int j0, int M, int Nc, int K, int lda, int ldb,
    int k0, int tid, int transB)
{
#pragma unroll
    for (int l = 0; l < 4; ++l) {
        int e = tid + l * 256;
        int row = e >> 3, q = e & 7;
        int gr = i0 + row; if (gr > M - 1) gr = M - 1;
        int gk = k0 + q * 8;
        int rem = K - gk;
        int bytes = rem >= 8 ? 16 : (rem > 0 ? rem * 2 : 0);
        cpa16(As + row * 72 + q * 8, Ab + (size_t)gr * lda + (bytes ? gk : 0), bytes);
    }
    if (transB) {
#pragma unroll
        for (int l = 0; l < 8; ++l) {
            int e = tid + l * 256;
            int row = e >> 3, q = e & 7;
            int gr = j0 + row; if (gr > Nc - 1) gr = Nc - 1;
            int gk = k0 + q * 8;
            int rem = K - gk;
            int bytes = rem >= 8 ? 16 : (rem > 0 ? rem * 2 : 0);
            cpa16(Bs + row * 72 + q * 8, Bb + (size_t)gr * ldb + (bytes ? gk : 0), bytes);
        }
    } else {
#pragma unroll
        for (int l = 0; l < 8; ++l) {
            int e = tid + l * 256;
            int kk = e >> 5;
            int nq = (e & 31) * 8;
            int gk = k0 + kk;
            int bytes = (gk < K) ? 16 : 0;
            cpa16(Bs + kk * 264 + nq, Bb + (size_t)(bytes ? gk : 0) * ldb + j0 + nq, bytes);
        }
    }
}

__global__ __launch_bounds__(256, 1) void hgemm(
    const __half* __restrict__ A, const __half* __restrict__ Bm,
    const float* __restrict__ bias, void* __restrict__ Cp,
    int M, int Nc, int K, int lda, int ldb, int ldc,
    long long sA, long long sB, long long sC,
    float alpha, int transB, int relu, int outHalf,
    int aksub, long long akstr)
{
    extern __shared__ __half smh[];
    const uint32_t sbase = (uint32_t)__cvta_generic_to_shared(smh);

    const __half* Ab = A  + (size_t)blockIdx.z * sA;
    const __half* Bb = Bm + (size_t)blockIdx.z * sB;

    const int tid  = threadIdx.x;
    const int lane = tid & 31;
    const int wid  = tid >> 5;
    const int wr   = (wid & 1) * 64;
    const int wc   = (wid >> 1) * 64;
    const int g    = lane >> 2;
    const int t    = lane & 3;

    const int i0 = blockIdx.y * 128;
    const int j0 = blockIdx.x * 256;

    float acc[4][8][4];
#pragma unroll
    for (int mi = 0; mi < 4; ++mi)
#pragma unroll
        for (int ni = 0; ni < 8; ++ni)
#pragma unroll
            for (int q = 0; q < 4; ++q) acc[mi][ni][q] = 0.f;

    const int nk = (K + 63) / 64;

#pragma unroll
    for (int s = 0; s < 2; ++s) {
        if (s < nk) {
            const __half* AbC = Ab + (aksub ? (long long)((s * 64) / aksub) * akstr : 0);
            load_chunk_h(smh + s * STG_H, smh + s * STG_H + AS_H, AbC, Bb,
                         i0, j0, M, Nc, K, lda, ldb, s * 64, tid, transB);
        }
        cp_commit();
    }

    // per-lane LDSM address components (element offsets within a stage)
    const int a_row = (lane & 15);          // + wr + mi*16
    const int a_ko  = 8 * (lane >> 4);      // + kb
    const int bt_row = (lane & 7) + 8 * ((lane >> 4) & 1);   // + cc0 (transB)
    const int bt_ko  = 8 * ((lane >> 3) & 1);                // + kb
    const int bn_row = (lane & 7) + 8 * ((lane >> 3) & 1);   // + kb (NN)
    const int bn_co  = 8 * (lane >> 4);                      // + cc0

    for (int c = 0; c < nk; ++c) {
        int pf = c + 2;
        if (pf < nk) {
            int st = pf % 3;
            const __half* AbC = Ab + (aksub ? (long long)((pf * 64) / aksub) * akstr : 0);
            load_chunk_h(smh + st * STG_H, smh + st * STG_H + AS_H, AbC, Bb,
                         i0, j0, M, Nc, K, lda, ldb, pf * 64, tid, transB);
        }
        cp_commit();
        cp_wait<2>();
        __syncthreads();

        const uint32_t aoff = sbase + (uint32_t)((c % 3) * STG_H) * 2;
        const uint32_t boff = aoff + AS_H * 2;

#pragma unroll
        for (int k16 = 0; k16 < 4; ++k16) {
            const int kb = k16 * 16;
            unsigned af[4][4];
#pragma unroll
            for (int mi = 0; mi < 4; ++mi) {
                uint32_t ad = aoff + (uint32_t)((wr + mi * 16 + a_row) * 72 + kb + a_ko) * 2;
                LDSM_X4(af[mi][0], af[mi][1], af[mi][2], af[mi][3], ad);
            }
            unsigned bf[8][2];
            if (transB) {
#pragma unroll
                for (int np = 0; np < 4; ++np) {
                    int cc0 = wc + np * 16;
                    uint32_t bd = boff + (uint32_t)((cc0 + bt_row) * 72 + kb + bt_ko) * 2;
                    LDSM_X4(bf[2 * np][0], bf[2 * np][1],
                            bf[2 * np + 1][0], bf[2 * np + 1][1], bd);
                }
            } else {
#pragma unroll
                for (int np = 0; np < 4; ++np) {
                    int cc0 = wc + np * 16;
                    uint32_t bd = boff + (uint32_t)((kb + bn_row) * 264 + cc0 + bn_co) * 2;
                    LDSM_X4_T(bf[2 * np][0], bf[2 * np][1],
                              bf[2 * np + 1][0], bf[2 * np + 1][1], bd);
                }
            }
#pragma unroll
            for (int mi = 0; mi < 4; ++mi)
#pragma unroll
                for (int ni = 0; ni < 8; ++ni)
                    mma_f16(acc[mi][ni], af[mi], bf[ni]);
        }
        __syncthreads();
    }
    cp_wait<0>();

    // epilogue
    float* Cf = (float*)Cp + (size_t)blockIdx.z * sC;
    __half* Ch = (__half*)Cp + (size_t)blockIdx.z * sC;
#pragma unroll
    for (int mi = 0; mi < 4; ++mi) {
        int r0 = i0 + wr + mi * 16 + g;
#pragma unroll
        for (int ni = 0; ni < 8; ++ni) {
            int c0 = j0 + wc + ni * 8 + 2 * t;
            float b0v = 0.f, b1v = 0.f;
            if (bias && c0 < Nc) { b0v = bias[c0]; b1v = (c0 + 1 < Nc) ? bias[c0 + 1] : 0.f; }
            float v00 = alpha * acc[mi][ni][0] + b0v;
            float v01 = alpha * acc[mi][ni][1] + b1v;
            float v10 = alpha * acc[mi][ni][2] + b0v;
            float v11 = alpha * acc[mi][ni][3] + b1v;
            if (relu) {
                v00 = fmaxf(v00, 0.f); v01 = fmaxf(v01, 0.f);
                v10 = fmaxf(v10, 0.f); v11 = fmaxf(v11, 0.f);
            }
            if (outHalf) {
                if (r0 < M && c0 < Nc)
                    *(__half2*)&Ch[(size_t)r0 * ldc + c0] = __floats2half2_rn(v00, v01);
                if (r0 + 8 < M && c0 < Nc)
                    *(__half2*)&Ch[(size_t)(r0 + 8) * ldc + c0] = __floats2half2_rn(v10, v11);
            } else {
                if (r0 < M) {
                    if (c0 < Nc)     Cf[(size_t)r0 * ldc + c0]     = v00;
                    if (c0 + 1 < Nc) Cf[(size_t)r0 * ldc + c0 + 1] = v01;
                }
                if (r0 + 8 < M) {
                    if (c0 < Nc)     Cf[(size_t)(r0 + 8) * ldc + c0]     = v10;
                    if (c0 + 1 < Nc) Cf[(size_t)(r0 + 8) * ldc + c0 + 1] = v11;
                }
            }
        }
    }
}

// ---------------- elementwise kernels ----------------

__global__ void cvt_h(const float* __restrict__ src, __half* __restrict__ dst, int n) {
    int i = blockIdx.x * 256 + threadIdx.x;
    if (i < n) dst[i] = __float2half(src[i]);
}

__global__ void trans_h(const float* __restrict__ h, const float* __restrict__ embed,
                        const float* __restrict__ mlt) {
    int b = blockIdx.z;
    int n0 = blockIdx.x * 32, c0 = blockIdx.y * 32;
    __shared__ float tile[32][33];
    int tx = threadIdx.x, ty = threadIdx.y;
#pragma unroll
    for (int l = 0; l < 4; ++l) {
        int c = c0 + ty + l * 8;
        int n = n0 + tx;
        tile[ty + l * 8][tx] = (n < N_) ? h[((size_t)b * D_ + c) * N_ + n] : 0.f;
    }
    __syncthreads();
#pragma unroll
    for (int l = 0; l < 4; ++l) {
        int n = n0 + ty + l * 8;
        if (n < N_) {
            int c = c0 + tx;
            float m = mlt[(size_t)b * N_ + n];
            float v = tile[tx][ty + l * 8] + embed[(size_t)n * D_ + c] * m;
            size_t idx = ((size_t)b * N_ + n) * D_ + c;
            g_s[idx] = v;
            g_sh[idx] = __float2half(v);
        }
    }
}

__global__ void trans_x(const float* __restrict__ x) {
    int b = blockIdx.z;
    int n0 = blockIdx.x * 32, c0 = blockIdx.y * 32;
    __shared__ float tile[32][33];
    int tx = threadIdx.x, ty = threadIdx.y;
#pragma unroll
    for (int l = 0; l < 4; ++l) {
        int c = c0 + ty + l * 8;
        int n = n0 + tx;
        tile[ty + l * 8][tx] = (n < N_) ? x[((size_t)b * DIN_ + c) * N_ + n] : 0.f;
    }
    __syncthreads();
#pragma unroll
    for (int l = 0; l < 4; ++l) {
        int n = n0 + ty + l * 8;
        if (n < N_)
            g_zh[((size_t)n * B_ + b) * CXG_ + c0 + tx] = __float2half(tile[tx][ty + l * 8]);
    }
}

__global__ void pad_adj(const float* __restrict__ adj) {
    int r = blockIdx.x, c = threadIdx.x;
    g_adjh[(size_t)r * SCLD + c] = __float2half((c < N_) ? adj[(size_t)r * N_ + c] : 0.f);
}

__global__ void concat_w(const float* __restrict__ Wu, const float* __restrict__ Wc) {
    int row = blockIdx.x, c = threadIdx.x;
#pragma unroll
    for (int l = 0; l < 5; ++l) {
        int k = c + l * 256;
        float v = (row < 256) ? Wu[(size_t)row * KC_ + k] : Wc[(size_t)(row - 256) * KC_ + k];
        g_wuch[(size_t)row * KC_ + k] = __float2half(v);
    }
}
__global__ void concat_b(const float* __restrict__ bu, const float* __restrict__ bc) {
    int o = threadIdx.x;
    g_buc[o] = (o < 256) ? bu[o] : bc[o - 256];
}

__global__ void softmax_rows(const float* __restrict__ sc, __half* __restrict__ sch) {
    int row = blockIdx.x * 8 + threadIdx.y;
    const float* p = sc + (size_t)row * SCLD;
    __half* ph = sch + (size_t)row * SCLD;
    int lane = threadIdx.x;
    float mx = -1e30f;
    for (int j = lane; j < N_; j += 32) mx = fmaxf(mx, p[j]);
#pragma unroll
    for (int o = 16; o > 0; o >>= 1) mx = fmaxf(mx, __shfl_xor_sync(0xffffffffu, mx, o));
    float sum = 0.f;
    float ev[7];
    int cnt = 0;
    for (int j = lane; j < N_; j += 32) { float e = expf(p[j] - mx); ev[cnt++] = e; sum += e; }
#pragma unroll
    for (int o = 16; o > 0; o >>= 1) sum += __shfl_xor_sync(0xffffffffu, sum, o);
    float inv = 1.f / sum;
    cnt = 0;
    for (int j = lane; j < N_; j += 32) ph[j] = __float2half(ev[cnt++] * inv);
}

// single-pass (sum, sumsq) LN reduction
__device__ __forceinline__ float2 ln_stats(float v, int c, float* red2) {
    float s = v, q = v * v;
#pragma unroll
    for (int o = 16; o > 0; o >>= 1) {
        s += __shfl_xor_sync(0xffffffffu, s, o);
        q += __shfl_xor_sync(0xffffffffu, q, o);
    }
    if ((c & 31) == 0) { red2[(c >> 5) * 2] = s; red2[(c >> 5) * 2 + 1] = q; }
    __syncthreads();
    float ts = 0.f, tq = 0.f;
#pragma unroll
    for (int w = 0; w < 8; ++w) { ts += red2[w * 2]; tq += red2[w * 2 + 1]; }
    float mu = ts * (1.f / 256.f);
    float var = tq * (1.f / 256.f) - mu * mu;
    return make_float2(mu, rsqrtf(var + 1e-5f));
}

__global__ void add_ln(const float* __restrict__ a, const float* __restrict__ bsrc,
                       const float* __restrict__ w, const float* __restrict__ bb,
                       float* __restrict__ outf, __half* __restrict__ outh) {
    int r = blockIdx.x, c = threadIdx.x;
    size_t idx = (size_t)r * D_ + c;
    float v = a[idx] + bsrc[idx];
    __shared__ float red2[16];
    float2 st = ln_stats(v, c, red2);
    float o = (v - st.x) * st.y * w[c] + bb[c];
    outf[idx] = o;
    outh[idx] = __float2half(o);
}

__global__ void ln2_make_h(const float* __restrict__ a, const float* __restrict__ bsrc,
                           const float* __restrict__ w, const float* __restrict__ bb,
                           const float* __restrict__ embed, const float* __restrict__ mlt,
                           const float* __restrict__ dt, const int* __restrict__ step) {
    int r = blockIdx.x, c = threadIdx.x;
    int b = r / N_, n = r % N_;
    size_t idx = (size_t)r * D_ + c;
    float v = a[idx] + bsrc[idx];
    __shared__ float red2[16];
    float2 st = ln_stats(v, c, red2);
    float s3v = (v - st.x) * st.y * w[c] + bb[c];

    float hv = g_s[idx] - embed[(size_t)n * D_ + c] * mlt[(size_t)b * N_ + n];
    float hn;
    if (*step != 0) {
        float d = dt[b];
        hn = sqrtf(1.f - d) * hv - sqrtf(d) * tanhf(s3v);
    } else {
        hn = hv;
    }
    g_hn[idx] = hn;
    g_zh[((size_t)n * B_ + b) * CXG_ + DIN_ + c] = __float2half(hn);
}

__global__ void final_combine(float* __restrict__ outp) {
    int b = blockIdx.z;
    int o0 = blockIdx.y * 32, n0 = blockIdx.x * 32;
    __shared__ float tbuf[32][33];
    int tx = threadIdx.x, ty = threadIdx.y;
#pragma unroll
    for (int s4 = 0; s4 < 4; ++s4) {
        int nl = ty + s4 * 8;
        int n = n0 + nl;
        float val = 0.f;
        if (n < N_) {
            size_t rp = (size_t)n * B_ + b;
            float gu = g_guc[rp * 512 + o0 + tx];
            float gc = g_guc[rp * 512 + 256 + o0 + tx];
            float uu = 1.f / (1.f + expf(-gu));
            float cc = tanhf(gc);
            val = uu * g_hn[((size_t)b * N_ + n) * D_ + o0 + tx] + (1.f - uu) * cc;
        }
        tbuf[nl][tx] = val;
    }
    __syncthreads();
#pragma unroll
    for (int s4 = 0; s4 < 4; ++s4) {
        int ol = ty + s4 * 8;
        int n = n0 + tx;
        if (n < N_)
            outp[((size_t)(b * D_ + o0 + ol)) * N_ + n] = tbuf[tx][ol];
    }
}

// ---------------- launcher ----------------
extern "C" void kernel_launch(void* const* d_in, const int* in_sizes, int n_in,
                              void* d_out, int out_size) {
    const float* x          = (const float*)d_in[0];
    const float* delta_t    = (const float*)d_in[1];
    const float* h          = (const float*)d_in[2];
    const float* adj        = (const float*)d_in[3];
    const float* mlt        = (const float*)d_in[5];
    const int*   step       = (const int*)d_in[7];
    const float* embed      = (const float*)d_in[8];
    const float* in_proj_w  = (const float*)d_in[9];
    const float* in_proj_b  = (const float*)d_in[10];
    const float* out_proj_w = (const float*)d_in[11];
    const float* out_proj_b = (const float*)d_in[12];
    const float* ln1_w      = (const float*)d_in[13];
    const float* ln1_b      = (const float*)d_in[14];
    const float* ln2_w      = (const float*)d_in[15];
    const float* ln2_b      = (const float*)d_in[16];
    const float* ffn_w1     = (const float*)d_in[17];
    const float* ffn_b1     = (const float*)d_in[18];
    const float* ffn_w2     = (const float*)d_in[19];
    const float* ffn_b2     = (const float*)d_in[20];
    const float* W_u        = (const float*)d_in[21];
    const float* b_u        = (const float*)d_in[22];
    const float* W_c        = (const float*)d_in[23];
    const float* b_c        = (const float*)d_in[24];
    float* outp = (float*)d_out;

    void *vp;
    cudaGetSymbolAddress(&vp, g_s);    float*  ps   = (float*)vp;
    cudaGetSymbolAddress(&vp, g_sh);   __half* psh  = (__half*)vp;
    cudaGetSymbolAddress(&vp, g_qkvh); __half* pqh  = (__half*)vp;
    cudaGetSymbolAddress(&vp, g_sc);   float*  psc  = (float*)vp;
    cudaGetSymbolAddress(&vp, g_sch);  __half* psch = (__half*)vp;
    cudaGetSymbolAddress(&vp, g_adjh); __half* padh = (__half*)vp;
    cudaGetSymbolAddress(&vp, g_oh);   __half* poh  = (__half*)vp;
    cudaGetSymbolAddress(&vp, g_f1);   float*  pf1  = (float*)vp;
    cudaGetSymbolAddress(&vp, g_s2);   float*  ps2  = (float*)vp;
    cudaGetSymbolAddress(&vp, g_s2h);  __half* ps2h = (__half*)vp;
    cudaGetSymbolAddress(&vp, g_poh);  __half* ppoh = (__half*)vp;
    cudaGetSymbolAddress(&vp, g_zh);   __half* pzh  = (__half*)vp;
    cudaGetSymbolAddress(&vp, g_guc);  float*  pguc = (float*)vp;
    cudaGetSymbolAddress(&vp, g_wuch); __half* pwuh = (__half*)vp;
    cudaGetSymbolAddress(&vp, g_buc);  float*  pbuc = (float*)vp;
    cudaGetSymbolAddress(&vp, g_wqh);  __half* pwq  = (__half*)vp;
    cudaGetSymbolAddress(&vp, g_woh);  __half* pwo  = (__half*)vp;
    cudaGetSymbolAddress(&vp, g_w1h);  __half* pw1  = (__half*)vp;
    cudaGetSymbolAddress(&vp, g_w2h);  __half* pw2  = (__half*)vp;

    static const int SMH = 3 * STG_H * 2;   // 165888 bytes
    cudaFuncSetAttribute(hgemm, cudaFuncAttributeMaxDynamicSharedMemorySize, SMH);

    // 0. prep: fp16 conversions
    pad_adj<<<N_, SCLD>>>(adj);
    concat_w<<<512, 256>>>(W_u, W_c);
    concat_b<<<1, 512>>>(b_u, b_c);
    cvt_h<<<(QKVLD * D_ + 255) / 256, 256>>>(in_proj_w, pwq, QKVLD * D_);
    cvt_h<<<(D_ * D_ + 255) / 256, 256>>>(out_proj_w, pwo, D_ * D_);
    cvt_h<<<(D_ * D_ + 255) / 256, 256>>>(ffn_w1, pw1, D_ * D_);
    cvt_h<<<(D_ * D_ + 255) / 256, 256>>>(ffn_w2, pw2, D_ * D_);

    // 1. transformer input + Z0 x-part
    trans_h<<<dim3(7, 8, B_), dim3(32, 8)>>>(h, embed, mlt);
    trans_x<<<dim3(7, 2, B_), dim3(32, 8)>>>(x);

    // 2. QKV -> fp16
    hgemm<<<dim3(3, 414, 1), 256, SMH>>>(psh, pwq, in_proj_b, pqh,
        NB_, QKVLD, 256, 256, 256, QKVLD, 0, 0, 0, 1.f, 1, 0, 1, 0, 0);

    // 3. scores: per-batch Q @ K^T / 16 -> fp32
    hgemm<<<dim3(1, 2, B_), 256, SMH>>>(pqh, pqh + 256, nullptr, psc,
        N_, N_, 256, QKVLD, QKVLD, SCLD,
        (long long)N_ * QKVLD, (long long)N_ * QKVLD, (long long)N_ * SCLD,
        1.f / 16.f, 1, 0, 0, 0, 0);

    // 4. softmax -> fp16
    softmax_rows<<<NB_ / 8, dim3(32, 8)>>>(psc, psch);

    // 5. attn @ V (NN) -> fp16
    hgemm<<<dim3(1, 2, B_), 256, SMH>>>(psch, pqh + 512, nullptr, poh,
        N_, 256, N_, SCLD, QKVLD, 256,
        (long long)N_ * SCLD, (long long)N_ * QKVLD, (long long)N_ * 256,
        1.f, 0, 0, 1, 0, 0);

    // 6. out projection -> fp32
    hgemm<<<dim3(1, 414, 1), 256, SMH>>>(poh, pwo, out_proj_b, pf1,
        NB_, 256, 256, 256, 256, 256, 0, 0, 0, 1.f, 1, 0, 0, 0, 0);

    // 7. LN1
    add_ln<<<NB_, 256>>>(ps, pf1, ln1_w, ln1_b, ps2, ps2h);

    // 8. FFN
    hgemm<<<dim3(1, 414, 1), 256, SMH>>>(ps2h, pw1, ffn_b1, ppoh,
        NB_, 256, 256, 256, 256, 256, 0, 0, 0, 1.f, 1, 1, 1, 0, 0);
    hgemm<<<dim3(1, 414, 1), 256, SMH>>>(ppoh, pw2, ffn_b2, pf1,
        NB_, 256, 256, 256, 256, 256, 0, 0, 0, 1.f, 1, 0, 0, 0, 0);

    // 9+10. LN2 + h update + Z0 h-part
    ln2_make_h<<<NB_, 256>>>(ps2, pf1, ln2_w, ln2_b, embed, mlt, delta_t, step);

    // 11. diffusion: Z_k = adj @ Z_{k-1}, dense NN (207 x 81920 x 207) -> fp16
    for (int k = 1; k <= 3; ++k) {
        hgemm<<<dim3(ZROW / 256, 2, 1), 256, SMH>>>(padh,
            pzh + (size_t)(k - 1) * ZK, nullptr, pzh + (size_t)k * ZK,
            N_, ZROW, N_, SCLD, ZROW, ZROW,
            0, 0, 0, 1.f, 0, 0, 1, 0, 0);
    }

    // 12. fused gates (blocked-K z) -> fp32
    hgemm<<<dim3(2, 414, 1), 256, SMH>>>(pzh, pwuh, pbuc, pguc,
        NB_, 512, KC_, CXG_, KC_, 512, 0, 0, 0, 1.f, 1, 0, 0,
        CXG_, (long long)ZK - CXG_);

    // 13. gated combine + transpose
    final_combine<<<dim3(7, 8, B_), dim3(32, 8)>>>(outp);
}